// round 13
// baseline (speedup 1.0000x reference)
#include <cuda_runtime.h>
#include <cstdint>

#define NMAX 40000
#define EMAX 640000

// Scratch (device globals: allocation-free per harness rules)
__device__ int   g_deg[NMAX];
__device__ int   g_rowptr[NMAX + 1];
__device__ int   g_cursor[NMAX];
__device__ int   g_col[EMAX];
__device__ float g_dinv[NMAX];
__device__ int   g_bsum[64];
__device__ float g_buf0[(size_t)NMAX * 128];
__device__ float g_buf1[(size_t)NMAX * 128];
// Pre-split tf32 fragment-ordered weights: ((kt*BN)+c)*4+qid -> {hi,lo,hi,lo}
__device__ float4 g_pb1[16 * 128 * 4];
__device__ float4 g_pb2[16 * 128 * 4];
__device__ float4 g_pb3[16 * 64 * 4];

// ---------------------------------------------------------------------------
__device__ __forceinline__ float trunc13(float f) {
    return __uint_as_float(__float_as_uint(f) & 0xffffe000u);
}

// ---------------------------------------------------------------------------
// 0) zero degree array
// ---------------------------------------------------------------------------
__global__ void zero_deg_kernel(int N) {
    int i = blockIdx.x * blockDim.x + threadIdx.x;
    if (i < N) g_deg[i] = 0;
}

// ---------------------------------------------------------------------------
// 1) degree count (edges by dst), 4 edges per thread via int4
// ---------------------------------------------------------------------------
__global__ void deg_kernel(const int* __restrict__ dst, int E, int N) {
    int i = blockIdx.x * blockDim.x + threadIdx.x;
    int e0 = i * 4;
    if (e0 + 4 <= E) {
        int4 d4 = *(const int4*)(dst + e0);
        atomicAdd(&g_deg[max(0, min(d4.x, N - 1))], 1);
        atomicAdd(&g_deg[max(0, min(d4.y, N - 1))], 1);
        atomicAdd(&g_deg[max(0, min(d4.z, N - 1))], 1);
        atomicAdd(&g_deg[max(0, min(d4.w, N - 1))], 1);
    } else {
        for (int e = e0; e < E; e++)
            atomicAdd(&g_deg[max(0, min(dst[e], N - 1))], 1);
    }
}

// ---------------------------------------------------------------------------
// 2) hierarchical exclusive scan -> rowptr/cursor + dinv
// ---------------------------------------------------------------------------
__global__ void scan1_kernel(int N) {
    __shared__ int sh[256];
    int t = threadIdx.x;
    int base = blockIdx.x * 1024 + t * 4;
    int s = 0;
    #pragma unroll
    for (int i = 0; i < 4; i++) if (base + i < N) s += g_deg[base + i];
    sh[t] = s;
    __syncthreads();
    #pragma unroll
    for (int off = 128; off > 0; off >>= 1) {
        if (t < off) sh[t] += sh[t + off];
        __syncthreads();
    }
    if (t == 0) g_bsum[blockIdx.x] = sh[0];
}

__global__ void scan2_kernel(int nb, int N) {
    if (threadIdx.x == 0) {
        int run = 0;
        for (int i = 0; i < nb; i++) { int v = g_bsum[i]; g_bsum[i] = run; run += v; }
        g_rowptr[N] = run;
    }
}

__global__ void scan3_kernel(int N) {
    __shared__ int sh[256];
    int t = threadIdx.x;
    int base = blockIdx.x * 1024 + t * 4;
    int v[4];
    int s = 0;
    #pragma unroll
    for (int i = 0; i < 4; i++) {
        v[i] = (base + i < N) ? g_deg[base + i] : 0;
        s += v[i];
    }
    sh[t] = s;
    __syncthreads();
    #pragma unroll
    for (int off = 1; off < 256; off <<= 1) {
        int x = (t >= off) ? sh[t - off] : 0;
        __syncthreads();
        sh[t] += x;
        __syncthreads();
    }
    int run = g_bsum[blockIdx.x] + sh[t] - s;
    #pragma unroll
    for (int i = 0; i < 4; i++) {
        int idx = base + i;
        if (idx < N) {
            g_rowptr[idx] = run;
            g_cursor[idx] = run;
            g_dinv[idx]   = rsqrtf((float)v[i] + 1.0f);
            run += v[i];
        }
    }
}

// ---------------------------------------------------------------------------
// 3) CSR fill, 4 edges per thread via int4
// ---------------------------------------------------------------------------
__global__ void fill_kernel(const int* __restrict__ src,
                            const int* __restrict__ dst, int E, int N) {
    int i = blockIdx.x * blockDim.x + threadIdx.x;
    int e0 = i * 4;
    if (e0 + 4 <= E) {
        int4 d4 = *(const int4*)(dst + e0);
        int4 s4 = *(const int4*)(src + e0);
        int p0 = atomicAdd(&g_cursor[max(0, min(d4.x, N - 1))], 1);
        int p1 = atomicAdd(&g_cursor[max(0, min(d4.y, N - 1))], 1);
        int p2 = atomicAdd(&g_cursor[max(0, min(d4.z, N - 1))], 1);
        int p3 = atomicAdd(&g_cursor[max(0, min(d4.w, N - 1))], 1);
        g_col[p0] = max(0, min(s4.x, N - 1));
        g_col[p1] = max(0, min(s4.y, N - 1));
        g_col[p2] = max(0, min(s4.z, N - 1));
        g_col[p3] = max(0, min(s4.w, N - 1));
    } else {
        for (int e = e0; e < E; e++) {
            int pos = atomicAdd(&g_cursor[max(0, min(dst[e], N - 1))], 1);
            g_col[pos] = max(0, min(src[e], N - 1));
        }
    }
}

// ---------------------------------------------------------------------------
// 3b) pack ALL weights into fragment-ordered split form, single launch
// ---------------------------------------------------------------------------
__device__ __forceinline__ void pack_one(const float* __restrict__ W,
                                         float4* __restrict__ PB, int BN, int i) {
    int qid = i & 3;
    int c   = (i >> 2) % BN;
    int kt  = (i >> 2) / BN;
    float f0 = W[(kt * 8 + qid) * BN + c];
    float f1 = W[(kt * 8 + qid + 4) * BN + c];
    float4 v;
    v.x = trunc13(f0); v.y = f0 - v.x;
    v.z = trunc13(f1); v.w = f1 - v.z;
    PB[i] = v;
}

__global__ void pack_all_kernel(const float* __restrict__ W1,
                                const float* __restrict__ W2,
                                const float* __restrict__ W3) {
    int i = blockIdx.x * blockDim.x + threadIdx.x;
    if (i < 16 * 128 * 4) { pack_one(W1, g_pb1, 128, i); return; }
    i -= 16 * 128 * 4;
    if (i < 16 * 128 * 4) { pack_one(W2, g_pb2, 128, i); return; }
    i -= 16 * 128 * 4;
    if (i < 16 * 64 * 4)  { pack_one(W3, g_pb3, 64, i); }
}

// ---------------------------------------------------------------------------
// 4) MMA helpers
// ---------------------------------------------------------------------------
__device__ __forceinline__ void mma_tf32(float* c, const unsigned* a, const unsigned* b) {
    asm volatile(
        "mma.sync.aligned.m16n8k8.row.col.f32.tf32.tf32.f32 "
        "{%0,%1,%2,%3}, {%4,%5,%6,%7}, {%8,%9}, {%0,%1,%2,%3};\n"
        : "+f"(c[0]), "+f"(c[1]), "+f"(c[2]), "+f"(c[3])
        : "r"(a[0]), "r"(a[1]), "r"(a[2]), "r"(a[3]), "r"(b[0]), "r"(b[1]));
}

#define A_STRIDE 132   // floats per row (128 + 4 pad -> conflict-free LDS)
#define A_SMEM_BYTES (128 * A_STRIDE * 4)

// shared gemm mainloop: reads A-tile from smem As, writes C[M,BN]
template <int BN>
__device__ __forceinline__ void gemm_from_smem(const float* As,
                                               const float4* __restrict__ PB,
                                               float* __restrict__ C,
                                               int m0, int M, int tid) {
    constexpr int NT = BN / 16;
    int wid = tid >> 5, lane = tid & 31;
    int warp_m = wid >> 1, warp_n = wid & 1;
    int grp = lane >> 2, qid = lane & 3;
    int col0 = warp_n * (BN / 2);

    float acc[2][NT][4];
    #pragma unroll
    for (int mt = 0; mt < 2; mt++)
        #pragma unroll
        for (int nt = 0; nt < NT; nt++)
            #pragma unroll
            for (int j = 0; j < 4; j++) acc[mt][nt][j] = 0.f;

    int ar0 = warp_m * 32 + grp;
    #pragma unroll 2
    for (int kt = 0; kt < 16; kt++) {
        int k0 = kt * 8;
        unsigned ahi[2][4], alo[2][4];
        #pragma unroll
        for (int mt = 0; mt < 2; mt++) {
            int r0 = ar0 + mt * 16;
            int r1 = r0 + 8;
            float f0 = As[r0 * A_STRIDE + k0 + qid];
            float f1 = As[r1 * A_STRIDE + k0 + qid];
            float f2 = As[r0 * A_STRIDE + k0 + qid + 4];
            float f3 = As[r1 * A_STRIDE + k0 + qid + 4];
            float h0 = trunc13(f0), h1 = trunc13(f1), h2 = trunc13(f2), h3 = trunc13(f3);
            ahi[mt][0] = __float_as_uint(h0); alo[mt][0] = __float_as_uint(f0 - h0);
            ahi[mt][1] = __float_as_uint(h1); alo[mt][1] = __float_as_uint(f1 - h1);
            ahi[mt][2] = __float_as_uint(h2); alo[mt][2] = __float_as_uint(f2 - h2);
            ahi[mt][3] = __float_as_uint(h3); alo[mt][3] = __float_as_uint(f3 - h3);
        }
        #pragma unroll
        for (int nt = 0; nt < NT; nt++) {
            int c = col0 + nt * 8 + grp;
            float4 pb = PB[((kt * BN) + c) * 4 + qid];
            unsigned bh[2] = { __float_as_uint(pb.x), __float_as_uint(pb.z) };
            unsigned bl[2] = { __float_as_uint(pb.y), __float_as_uint(pb.w) };
            #pragma unroll
            for (int mt = 0; mt < 2; mt++) {
                mma_tf32(acc[mt][nt], ahi[mt], bh);
                mma_tf32(acc[mt][nt], ahi[mt], bl);
                mma_tf32(acc[mt][nt], alo[mt], bh);
            }
        }
    }
    #pragma unroll
    for (int mt = 0; mt < 2; mt++) {
        int r0 = m0 + warp_m * 32 + mt * 16 + grp;
        int r1 = r0 + 8;
        #pragma unroll
        for (int nt = 0; nt < NT; nt++) {
            int c = col0 + nt * 8 + qid * 2;
            if (r0 < M) {
                C[(size_t)r0 * BN + c]     = acc[mt][nt][0];
                C[(size_t)r0 * BN + c + 1] = acc[mt][nt][1];
            }
            if (r1 < M) {
                C[(size_t)r1 * BN + c]     = acc[mt][nt][2];
                C[(size_t)r1 * BN + c + 1] = acc[mt][nt][3];
            }
        }
    }
}

// ---------------------------------------------------------------------------
// 4a) plain GEMM (layer 1): stage A from global, then mainloop
// ---------------------------------------------------------------------------
template <int BN>
__global__ void __launch_bounds__(256, 1)
mma_gemm_kernel(const float* __restrict__ A,
                const float4* __restrict__ PB,
                float* __restrict__ C, int M) {
    extern __shared__ float As[];
    int tid = threadIdx.x;
    int m0 = blockIdx.x * 128;
    for (int idx = tid; idx < 128 * 32; idx += 256) {
        int r = idx >> 5;
        int c4 = (idx & 31) * 4;
        int gr = min(m0 + r, M - 1);
        *(float4*)(As + r * A_STRIDE + c4) = *(const float4*)(A + (size_t)gr * 128 + c4);
    }
    __syncthreads();
    gemm_from_smem<BN>(As, PB, C, m0, M, tid);
}

// ---------------------------------------------------------------------------
// 4b) FUSED agg(D=128) + GEMM: block aggregates its 128 nodes into the smem
//     A-tile (bias+ReLU applied), then runs the gemm mainloop from smem.
// ---------------------------------------------------------------------------
template <int BN>
__global__ void __launch_bounds__(256, 1)
fused_agg_gemm_kernel(const float* __restrict__ hin,
                      const float* __restrict__ bias,
                      const float4* __restrict__ PB,
                      float* __restrict__ C, int M) {
    extern __shared__ float As[];
    int tid = threadIdx.x;
    int wid = tid >> 5, lane = tid & 31;
    int m0 = blockIdx.x * 128;

    float4 b = *(const float4*)(bias + lane * 4);

    // phase 1: aggregate 16 nodes per warp into As rows (bias + ReLU)
    for (int i = 0; i < 16; i++) {
        int r = wid * 16 + i;
        int node = min(m0 + r, M - 1);
        float dn = g_dinv[node];
        float acc[4];
        {
            float ws = dn * dn;
            float4 v = *(const float4*)(hin + (size_t)node * 128 + lane * 4);
            acc[0] = ws * v.x; acc[1] = ws * v.y; acc[2] = ws * v.z; acc[3] = ws * v.w;
        }
        int e = g_rowptr[node];
        const int e1 = g_rowptr[node + 1];
        for (; e + 4 <= e1; e += 4) {
            int s0 = g_col[e], s1 = g_col[e + 1], s2 = g_col[e + 2], s3 = g_col[e + 3];
            float w0 = g_dinv[s0] * dn, w1 = g_dinv[s1] * dn;
            float w2 = g_dinv[s2] * dn, w3 = g_dinv[s3] * dn;
            float4 v0 = *(const float4*)(hin + (size_t)s0 * 128 + lane * 4);
            float4 v1 = *(const float4*)(hin + (size_t)s1 * 128 + lane * 4);
            float4 v2 = *(const float4*)(hin + (size_t)s2 * 128 + lane * 4);
            float4 v3 = *(const float4*)(hin + (size_t)s3 * 128 + lane * 4);
            acc[0] += w0 * v0.x + w1 * v1.x + w2 * v2.x + w3 * v3.x;
            acc[1] += w0 * v0.y + w1 * v1.y + w2 * v2.y + w3 * v3.y;
            acc[2] += w0 * v0.z + w1 * v1.z + w2 * v2.z + w3 * v3.z;
            acc[3] += w0 * v0.w + w1 * v1.w + w2 * v2.w + w3 * v3.w;
        }
        for (; e < e1; e++) {
            int s = g_col[e];
            float w = g_dinv[s] * dn;
            float4 v = *(const float4*)(hin + (size_t)s * 128 + lane * 4);
            acc[0] += w * v.x; acc[1] += w * v.y; acc[2] += w * v.z; acc[3] += w * v.w;
        }
        float4 o = make_float4(fmaxf(acc[0] + b.x, 0.f), fmaxf(acc[1] + b.y, 0.f),
                               fmaxf(acc[2] + b.z, 0.f), fmaxf(acc[3] + b.w, 0.f));
        *(float4*)(As + r * A_STRIDE + lane * 4) = o;
    }
    __syncthreads();

    // phase 2: gemm from smem
    gemm_from_smem<BN>(As, PB, C, m0, M, tid);
}

// ---------------------------------------------------------------------------
// 5b) Aggregation D=64 with fused output head (unroll 4)
// ---------------------------------------------------------------------------
__global__ void agg64_out_kernel(const float* __restrict__ hin,
                                 float* __restrict__ hout,
                                 const float* __restrict__ bias,
                                 const float* __restrict__ Wout,
                                 const float* __restrict__ bout,
                                 float* __restrict__ out, int N) {
    int warp = (blockIdx.x * blockDim.x + threadIdx.x) >> 5;
    int lane = threadIdx.x & 31;
    if (warp >= N) return;

    float dn = g_dinv[warp];
    float a0, a1;
    {
        float ws = dn * dn;
        float2 v = *(const float2*)(hin + (size_t)warp * 64 + lane * 2);
        a0 = ws * v.x; a1 = ws * v.y;
    }
    int e = g_rowptr[warp];
    const int e1 = g_rowptr[warp + 1];
    for (; e + 4 <= e1; e += 4) {
        int s0 = g_col[e], s1 = g_col[e + 1], s2 = g_col[e + 2], s3 = g_col[e + 3];
        float w0 = g_dinv[s0] * dn, w1 = g_dinv[s1] * dn;
        float w2 = g_dinv[s2] * dn, w3 = g_dinv[s3] * dn;
        float2 v0 = *(const float2*)(hin + (size_t)s0 * 64 + lane * 2);
        float2 v1 = *(const float2*)(hin + (size_t)s1 * 64 + lane * 2);
        float2 v2 = *(const float2*)(hin + (size_t)s2 * 64 + lane * 2);
        float2 v3 = *(const float2*)(hin + (size_t)s3 * 64 + lane * 2);
        a0 += w0 * v0.x + w1 * v1.x + w2 * v2.x + w3 * v3.x;
        a1 += w0 * v0.y + w1 * v1.y + w2 * v2.y + w3 * v3.y;
    }
    for (; e < e1; e++) {
        int s = g_col[e];
        float w = g_dinv[s] * dn;
        float2 v = *(const float2*)(hin + (size_t)s * 64 + lane * 2);
        a0 += w * v.x; a1 += w * v.y;
    }
    float2 b = *(const float2*)(bias + lane * 2);
    float2 o = make_float2(a0 + b.x, a1 + b.y);
    *(float2*)(hout + (size_t)warp * 64 + lane * 2) = o;

    int c0 = lane * 2;
    float p0 = o.x * __ldg(&Wout[c0 * 2])     + o.y * __ldg(&Wout[(c0 + 1) * 2]);
    float p1 = o.x * __ldg(&Wout[c0 * 2 + 1]) + o.y * __ldg(&Wout[(c0 + 1) * 2 + 1]);
    #pragma unroll
    for (int off = 16; off > 0; off >>= 1) {
        p0 += __shfl_xor_sync(0xffffffffu, p0, off);
        p1 += __shfl_xor_sync(0xffffffffu, p1, off);
    }
    if (lane == 0) {
        out[(size_t)warp * 2 + 0] = p0 + __ldg(&bout[0]);
        out[(size_t)warp * 2 + 1] = p1 + __ldg(&bout[1]);
    }
}

// ---------------------------------------------------------------------------
extern "C" void kernel_launch(void* const* d_in, const int* in_sizes, int n_in,
                              void* d_out, int out_size) {
    (void)n_in; (void)out_size;
    const float* x    = (const float*)d_in[0];
    const int*   ei   = (const int*)d_in[1];   // int32 (JAX default x64 off)
    const float* W1   = (const float*)d_in[2];
    const float* b1   = (const float*)d_in[3];
    const float* W2   = (const float*)d_in[4];
    const float* b2   = (const float*)d_in[5];
    const float* W3   = (const float*)d_in[6];
    const float* b3   = (const float*)d_in[7];
    const float* Wout = (const float*)d_in[8];
    const float* bout = (const float*)d_in[9];

    int N = in_sizes[0] / 128;
    int E = in_sizes[1] / 2;

    float* out  = (float*)d_out;
    float* hout = out + (size_t)N * 2;   // tuple layout: out[N,2] then h[N,64]

    float* buf0; cudaGetSymbolAddress((void**)&buf0, g_buf0);
    float* buf1; cudaGetSymbolAddress((void**)&buf1, g_buf1);
    float4* pb1; cudaGetSymbolAddress((void**)&pb1, g_pb1);
    float4* pb2; cudaGetSymbolAddress((void**)&pb2, g_pb2);
    float4* pb3; cudaGetSymbolAddress((void**)&pb3, g_pb3);

    const int* src = ei;
    const int* dst = ei + E;

    // one-time host-side setup (attrs, side stream, fork/join events)
    static cudaStream_t s2 = nullptr;
    static cudaEvent_t ev_fork = nullptr, ev_join = nullptr;
    if (!s2) {
        cudaFuncSetAttribute(mma_gemm_kernel<128>,
                             cudaFuncAttributeMaxDynamicSharedMemorySize, A_SMEM_BYTES);
        cudaFuncSetAttribute(fused_agg_gemm_kernel<128>,
                             cudaFuncAttributeMaxDynamicSharedMemorySize, A_SMEM_BYTES);
        cudaFuncSetAttribute(fused_agg_gemm_kernel<64>,
                             cudaFuncAttributeMaxDynamicSharedMemorySize, A_SMEM_BYTES);
        cudaStreamCreateWithFlags(&s2, cudaStreamNonBlocking);
        cudaEventCreateWithFlags(&ev_fork, cudaEventDisableTiming);
        cudaEventCreateWithFlags(&ev_join, cudaEventDisableTiming);
    }

    int nb = (N + 1023) / 1024;
    int e4 = (E + 3) / 4;
    int gM = (N + 127) / 128;
    int gW = (N * 32 + 255) / 256;
    int packTotal = 16 * 128 * 4 + 16 * 128 * 4 + 16 * 64 * 4;

    // ---- fork: side stream runs weight packing + GEMM1 (independent of CSR) ----
    cudaEventRecord(ev_fork, 0);
    cudaStreamWaitEvent(s2, ev_fork, 0);

    // branch B (s2): pack_all -> gemm1
    pack_all_kernel<<<(packTotal + 255) / 256, 256, 0, s2>>>(W1, W2, W3);
    mma_gemm_kernel<128><<<gM, 256, A_SMEM_BYTES, s2>>>(x, pb1, buf0, N);
    cudaEventRecord(ev_join, s2);

    // branch A (capture stream): CSR build
    zero_deg_kernel<<<(N + 255) / 256, 256>>>(N);
    deg_kernel<<<(e4 + 255) / 256, 256>>>(dst, E, N);
    scan1_kernel<<<nb, 256>>>(N);
    scan2_kernel<<<1, 32>>>(nb, N);
    scan3_kernel<<<nb, 256>>>(N);
    fill_kernel<<<(e4 + 255) / 256, 256>>>(src, dst, E, N);

    // ---- join ----
    cudaStreamWaitEvent(0, ev_join, 0);

    // fused layer transitions: agg1+gemm2, agg2+gemm3
    fused_agg_gemm_kernel<128><<<gM, 256, A_SMEM_BYTES>>>(buf0, b1, pb2, buf1, N);
    fused_agg_gemm_kernel<64><<<gM, 256, A_SMEM_BYTES>>>(buf1, b2, pb3, buf0, N);
    // final: agg3 (D=64, no relu) + output head
    agg64_out_kernel<<<gW, 256>>>(buf0, hout, b3, Wout, bout, out, N);
}

// round 14
// speedup vs baseline: 1.1649x; 1.1649x over previous
#include <cuda_runtime.h>
#include <cstdint>

#define NMAX 40000
#define EMAX 640000

// Scratch (device globals: allocation-free per harness rules)
__device__ int   g_deg[NMAX];
__device__ int   g_rowptr[NMAX + 1];
__device__ int   g_cursor[NMAX];
__device__ int   g_col[EMAX];
__device__ float g_dinv[NMAX];
__device__ int   g_bsum[64];
__device__ float g_buf0[(size_t)NMAX * 128];
__device__ float g_buf1[(size_t)NMAX * 128];
__device__ float g_buf2[(size_t)NMAX * 128];
// Pre-split tf32 fragment-ordered weights: ((kt*BN)+c)*4+qid -> {hi,lo,hi,lo}
__device__ float4 g_pb1[16 * 128 * 4];
__device__ float4 g_pb2[16 * 128 * 4];
__device__ float4 g_pb3[16 * 64 * 4];

// ---------------------------------------------------------------------------
__device__ __forceinline__ float trunc13(float f) {
    return __uint_as_float(__float_as_uint(f) & 0xffffe000u);
}

// ---------------------------------------------------------------------------
// 0) zero degree array
// ---------------------------------------------------------------------------
__global__ void zero_deg_kernel(int N) {
    int i = blockIdx.x * blockDim.x + threadIdx.x;
    if (i < N) g_deg[i] = 0;
}

// ---------------------------------------------------------------------------
// 1) degree count (edges by dst), 4 edges per thread via int4
// ---------------------------------------------------------------------------
__global__ void deg_kernel(const int* __restrict__ dst, int E, int N) {
    int i = blockIdx.x * blockDim.x + threadIdx.x;
    int e0 = i * 4;
    if (e0 + 4 <= E) {
        int4 d4 = *(const int4*)(dst + e0);
        atomicAdd(&g_deg[max(0, min(d4.x, N - 1))], 1);
        atomicAdd(&g_deg[max(0, min(d4.y, N - 1))], 1);
        atomicAdd(&g_deg[max(0, min(d4.z, N - 1))], 1);
        atomicAdd(&g_deg[max(0, min(d4.w, N - 1))], 1);
    } else {
        for (int e = e0; e < E; e++)
            atomicAdd(&g_deg[max(0, min(dst[e], N - 1))], 1);
    }
}

// ---------------------------------------------------------------------------
// 2) hierarchical exclusive scan -> rowptr/cursor + dinv
// ---------------------------------------------------------------------------
__global__ void scan1_kernel(int N) {
    __shared__ int sh[256];
    int t = threadIdx.x;
    int base = blockIdx.x * 1024 + t * 4;
    int s = 0;
    #pragma unroll
    for (int i = 0; i < 4; i++) if (base + i < N) s += g_deg[base + i];
    sh[t] = s;
    __syncthreads();
    #pragma unroll
    for (int off = 128; off > 0; off >>= 1) {
        if (t < off) sh[t] += sh[t + off];
        __syncthreads();
    }
    if (t == 0) g_bsum[blockIdx.x] = sh[0];
}

__global__ void scan2_kernel(int nb, int N) {
    if (threadIdx.x == 0) {
        int run = 0;
        for (int i = 0; i < nb; i++) { int v = g_bsum[i]; g_bsum[i] = run; run += v; }
        g_rowptr[N] = run;
    }
}

__global__ void scan3_kernel(int N) {
    __shared__ int sh[256];
    int t = threadIdx.x;
    int base = blockIdx.x * 1024 + t * 4;
    int v[4];
    int s = 0;
    #pragma unroll
    for (int i = 0; i < 4; i++) {
        v[i] = (base + i < N) ? g_deg[base + i] : 0;
        s += v[i];
    }
    sh[t] = s;
    __syncthreads();
    #pragma unroll
    for (int off = 1; off < 256; off <<= 1) {
        int x = (t >= off) ? sh[t - off] : 0;
        __syncthreads();
        sh[t] += x;
        __syncthreads();
    }
    int run = g_bsum[blockIdx.x] + sh[t] - s;
    #pragma unroll
    for (int i = 0; i < 4; i++) {
        int idx = base + i;
        if (idx < N) {
            g_rowptr[idx] = run;
            g_cursor[idx] = run;
            g_dinv[idx]   = rsqrtf((float)v[i] + 1.0f);
            run += v[i];
        }
    }
}

// ---------------------------------------------------------------------------
// 3) CSR fill, 4 edges per thread via int4
// ---------------------------------------------------------------------------
__global__ void fill_kernel(const int* __restrict__ src,
                            const int* __restrict__ dst, int E, int N) {
    int i = blockIdx.x * blockDim.x + threadIdx.x;
    int e0 = i * 4;
    if (e0 + 4 <= E) {
        int4 d4 = *(const int4*)(dst + e0);
        int4 s4 = *(const int4*)(src + e0);
        int p0 = atomicAdd(&g_cursor[max(0, min(d4.x, N - 1))], 1);
        int p1 = atomicAdd(&g_cursor[max(0, min(d4.y, N - 1))], 1);
        int p2 = atomicAdd(&g_cursor[max(0, min(d4.z, N - 1))], 1);
        int p3 = atomicAdd(&g_cursor[max(0, min(d4.w, N - 1))], 1);
        g_col[p0] = max(0, min(s4.x, N - 1));
        g_col[p1] = max(0, min(s4.y, N - 1));
        g_col[p2] = max(0, min(s4.z, N - 1));
        g_col[p3] = max(0, min(s4.w, N - 1));
    } else {
        for (int e = e0; e < E; e++) {
            int pos = atomicAdd(&g_cursor[max(0, min(dst[e], N - 1))], 1);
            g_col[pos] = max(0, min(src[e], N - 1));
        }
    }
}

// ---------------------------------------------------------------------------
// 3b) pack ALL weights into fragment-ordered split form, single launch
// ---------------------------------------------------------------------------
__device__ __forceinline__ void pack_one(const float* __restrict__ W,
                                         float4* __restrict__ PB, int BN, int i) {
    int qid = i & 3;
    int c   = (i >> 2) % BN;
    int kt  = (i >> 2) / BN;
    float f0 = W[(kt * 8 + qid) * BN + c];
    float f1 = W[(kt * 8 + qid + 4) * BN + c];
    float4 v;
    v.x = trunc13(f0); v.y = f0 - v.x;
    v.z = trunc13(f1); v.w = f1 - v.z;
    PB[i] = v;
}

__global__ void pack_all_kernel(const float* __restrict__ W1,
                                const float* __restrict__ W2,
                                const float* __restrict__ W3) {
    int i = blockIdx.x * blockDim.x + threadIdx.x;
    if (i < 16 * 128 * 4) { pack_one(W1, g_pb1, 128, i); return; }
    i -= 16 * 128 * 4;
    if (i < 16 * 128 * 4) { pack_one(W2, g_pb2, 128, i); return; }
    i -= 16 * 128 * 4;
    if (i < 16 * 64 * 4)  { pack_one(W3, g_pb3, 64, i); }
}

// ---------------------------------------------------------------------------
// 4) Tensor-core GEMM, 3xTF32, A staged through shared memory; node-range base
// ---------------------------------------------------------------------------
__device__ __forceinline__ void mma_tf32(float* c, const unsigned* a, const unsigned* b) {
    asm volatile(
        "mma.sync.aligned.m16n8k8.row.col.f32.tf32.tf32.f32 "
        "{%0,%1,%2,%3}, {%4,%5,%6,%7}, {%8,%9}, {%0,%1,%2,%3};\n"
        : "+f"(c[0]), "+f"(c[1]), "+f"(c[2]), "+f"(c[3])
        : "r"(a[0]), "r"(a[1]), "r"(a[2]), "r"(a[3]), "r"(b[0]), "r"(b[1]));
}

#define A_STRIDE 132   // floats per row (128 + 4 pad -> conflict-free LDS)
#define A_SMEM_BYTES (128 * A_STRIDE * 4)

template <int BN>
__global__ void __launch_bounds__(256, 1)
mma_gemm_kernel(const float* __restrict__ A,
                const float4* __restrict__ PB,
                float* __restrict__ C, int M, int base) {
    constexpr int NT = BN / 16;
    extern __shared__ float As[];
    int tid = threadIdx.x;
    int wid = tid >> 5, lane = tid & 31;
    int warp_m = wid >> 1, warp_n = wid & 1;
    int grp = lane >> 2, qid = lane & 3;
    int m0 = base + blockIdx.x * 128;
    int col0 = warp_n * (BN / 2);

    // stage A tile: coalesced float4 loads
    for (int idx = tid; idx < 128 * 32; idx += 256) {
        int r = idx >> 5;
        int c4 = (idx & 31) * 4;
        int gr = min(m0 + r, M - 1);
        *(float4*)(As + r * A_STRIDE + c4) = *(const float4*)(A + (size_t)gr * 128 + c4);
    }
    __syncthreads();

    float acc[2][NT][4];
    #pragma unroll
    for (int mt = 0; mt < 2; mt++)
        #pragma unroll
        for (int nt = 0; nt < NT; nt++)
            #pragma unroll
            for (int j = 0; j < 4; j++) acc[mt][nt][j] = 0.f;

    int ar0 = warp_m * 32 + grp;
    #pragma unroll 2
    for (int kt = 0; kt < 16; kt++) {
        int k0 = kt * 8;
        unsigned ahi[2][4], alo[2][4];
        #pragma unroll
        for (int mt = 0; mt < 2; mt++) {
            int r0 = ar0 + mt * 16;
            int r1 = r0 + 8;
            float f0 = As[r0 * A_STRIDE + k0 + qid];
            float f1 = As[r1 * A_STRIDE + k0 + qid];
            float f2 = As[r0 * A_STRIDE + k0 + qid + 4];
            float f3 = As[r1 * A_STRIDE + k0 + qid + 4];
            float h0 = trunc13(f0), h1 = trunc13(f1), h2 = trunc13(f2), h3 = trunc13(f3);
            ahi[mt][0] = __float_as_uint(h0); alo[mt][0] = __float_as_uint(f0 - h0);
            ahi[mt][1] = __float_as_uint(h1); alo[mt][1] = __float_as_uint(f1 - h1);
            ahi[mt][2] = __float_as_uint(h2); alo[mt][2] = __float_as_uint(f2 - h2);
            ahi[mt][3] = __float_as_uint(h3); alo[mt][3] = __float_as_uint(f3 - h3);
        }
        #pragma unroll
        for (int nt = 0; nt < NT; nt++) {
            int c = col0 + nt * 8 + grp;
            float4 pb = PB[((kt * BN) + c) * 4 + qid];
            unsigned bh[2] = { __float_as_uint(pb.x), __float_as_uint(pb.z) };
            unsigned bl[2] = { __float_as_uint(pb.y), __float_as_uint(pb.w) };
            #pragma unroll
            for (int mt = 0; mt < 2; mt++) {
                mma_tf32(acc[mt][nt], ahi[mt], bh);
                mma_tf32(acc[mt][nt], ahi[mt], bl);
                mma_tf32(acc[mt][nt], alo[mt], bh);
            }
        }
    }
    #pragma unroll
    for (int mt = 0; mt < 2; mt++) {
        int r0 = m0 + warp_m * 32 + mt * 16 + grp;
        int r1 = r0 + 8;
        #pragma unroll
        for (int nt = 0; nt < NT; nt++) {
            int c = col0 + nt * 8 + qid * 2;
            if (r0 < M) {
                C[(size_t)r0 * BN + c]     = acc[mt][nt][0];
                C[(size_t)r0 * BN + c + 1] = acc[mt][nt][1];
            }
            if (r1 < M) {
                C[(size_t)r1 * BN + c]     = acc[mt][nt][2];
                C[(size_t)r1 * BN + c + 1] = acc[mt][nt][3];
            }
        }
    }
}

// ---------------------------------------------------------------------------
// 5) Aggregation D=128: warp per node over range [n0, n1)
// ---------------------------------------------------------------------------
template <bool RELU>
__global__ void agg128_kernel(const float* __restrict__ hin,
                              float* __restrict__ hout,
                              const float* __restrict__ bias, int n0, int n1) {
    int warp = n0 + ((blockIdx.x * blockDim.x + threadIdx.x) >> 5);
    int lane = threadIdx.x & 31;
    if (warp >= n1) return;

    float dn = g_dinv[warp];
    float acc[4];
    {
        float ws = dn * dn;
        float4 v = *(const float4*)(hin + (size_t)warp * 128 + lane * 4);
        acc[0] = ws * v.x; acc[1] = ws * v.y; acc[2] = ws * v.z; acc[3] = ws * v.w;
    }
    int e = g_rowptr[warp];
    const int e1 = g_rowptr[warp + 1];
    for (; e + 4 <= e1; e += 4) {
        int s0 = g_col[e], s1 = g_col[e + 1], s2 = g_col[e + 2], s3 = g_col[e + 3];
        float w0 = g_dinv[s0] * dn, w1 = g_dinv[s1] * dn;
        float w2 = g_dinv[s2] * dn, w3 = g_dinv[s3] * dn;
        float4 v0 = *(const float4*)(hin + (size_t)s0 * 128 + lane * 4);
        float4 v1 = *(const float4*)(hin + (size_t)s1 * 128 + lane * 4);
        float4 v2 = *(const float4*)(hin + (size_t)s2 * 128 + lane * 4);
        float4 v3 = *(const float4*)(hin + (size_t)s3 * 128 + lane * 4);
        acc[0] += w0 * v0.x + w1 * v1.x + w2 * v2.x + w3 * v3.x;
        acc[1] += w0 * v0.y + w1 * v1.y + w2 * v2.y + w3 * v3.y;
        acc[2] += w0 * v0.z + w1 * v1.z + w2 * v2.z + w3 * v3.z;
        acc[3] += w0 * v0.w + w1 * v1.w + w2 * v2.w + w3 * v3.w;
    }
    for (; e < e1; e++) {
        int s = g_col[e];
        float w = g_dinv[s] * dn;
        float4 v = *(const float4*)(hin + (size_t)s * 128 + lane * 4);
        acc[0] += w * v.x; acc[1] += w * v.y; acc[2] += w * v.z; acc[3] += w * v.w;
    }
    float4 b = *(const float4*)(bias + lane * 4);
    float4 o = make_float4(acc[0] + b.x, acc[1] + b.y, acc[2] + b.z, acc[3] + b.w);
    if (RELU) {
        o.x = fmaxf(o.x, 0.f); o.y = fmaxf(o.y, 0.f);
        o.z = fmaxf(o.z, 0.f); o.w = fmaxf(o.w, 0.f);
    }
    *(float4*)(hout + (size_t)warp * 128 + lane * 4) = o;
}

// ---------------------------------------------------------------------------
// 5b) Aggregation D=64 with fused output head (full range)
// ---------------------------------------------------------------------------
__global__ void agg64_out_kernel(const float* __restrict__ hin,
                                 float* __restrict__ hout,
                                 const float* __restrict__ bias,
                                 const float* __restrict__ Wout,
                                 const float* __restrict__ bout,
                                 float* __restrict__ out, int N) {
    int warp = (blockIdx.x * blockDim.x + threadIdx.x) >> 5;
    int lane = threadIdx.x & 31;
    if (warp >= N) return;

    float dn = g_dinv[warp];
    float a0, a1;
    {
        float ws = dn * dn;
        float2 v = *(const float2*)(hin + (size_t)warp * 64 + lane * 2);
        a0 = ws * v.x; a1 = ws * v.y;
    }
    int e = g_rowptr[warp];
    const int e1 = g_rowptr[warp + 1];
    for (; e + 4 <= e1; e += 4) {
        int s0 = g_col[e], s1 = g_col[e + 1], s2 = g_col[e + 2], s3 = g_col[e + 3];
        float w0 = g_dinv[s0] * dn, w1 = g_dinv[s1] * dn;
        float w2 = g_dinv[s2] * dn, w3 = g_dinv[s3] * dn;
        float2 v0 = *(const float2*)(hin + (size_t)s0 * 64 + lane * 2);
        float2 v1 = *(const float2*)(hin + (size_t)s1 * 64 + lane * 2);
        float2 v2 = *(const float2*)(hin + (size_t)s2 * 64 + lane * 2);
        float2 v3 = *(const float2*)(hin + (size_t)s3 * 64 + lane * 2);
        a0 += w0 * v0.x + w1 * v1.x + w2 * v2.x + w3 * v3.x;
        a1 += w0 * v0.y + w1 * v1.y + w2 * v2.y + w3 * v3.y;
    }
    for (; e < e1; e++) {
        int s = g_col[e];
        float w = g_dinv[s] * dn;
        float2 v = *(const float2*)(hin + (size_t)s * 64 + lane * 2);
        a0 += w * v.x; a1 += w * v.y;
    }
    float2 b = *(const float2*)(bias + lane * 2);
    float2 o = make_float2(a0 + b.x, a1 + b.y);
    *(float2*)(hout + (size_t)warp * 64 + lane * 2) = o;

    int c0 = lane * 2;
    float p0 = o.x * __ldg(&Wout[c0 * 2])     + o.y * __ldg(&Wout[(c0 + 1) * 2]);
    float p1 = o.x * __ldg(&Wout[c0 * 2 + 1]) + o.y * __ldg(&Wout[(c0 + 1) * 2 + 1]);
    #pragma unroll
    for (int off = 16; off > 0; off >>= 1) {
        p0 += __shfl_xor_sync(0xffffffffu, p0, off);
        p1 += __shfl_xor_sync(0xffffffffu, p1, off);
    }
    if (lane == 0) {
        out[(size_t)warp * 2 + 0] = p0 + __ldg(&bout[0]);
        out[(size_t)warp * 2 + 1] = p1 + __ldg(&bout[1]);
    }
}

// ---------------------------------------------------------------------------
extern "C" void kernel_launch(void* const* d_in, const int* in_sizes, int n_in,
                              void* d_out, int out_size) {
    (void)n_in; (void)out_size;
    const float* x    = (const float*)d_in[0];
    const int*   ei   = (const int*)d_in[1];   // int32 (JAX default x64 off)
    const float* W1   = (const float*)d_in[2];
    const float* b1   = (const float*)d_in[3];
    const float* W2   = (const float*)d_in[4];
    const float* b2   = (const float*)d_in[5];
    const float* W3   = (const float*)d_in[6];
    const float* b3   = (const float*)d_in[7];
    const float* Wout = (const float*)d_in[8];
    const float* bout = (const float*)d_in[9];

    int N = in_sizes[0] / 128;
    int E = in_sizes[1] / 2;

    float* out  = (float*)d_out;
    float* hout = out + (size_t)N * 2;   // tuple layout: out[N,2] then h[N,64]

    float* buf0; cudaGetSymbolAddress((void**)&buf0, g_buf0);
    float* buf1; cudaGetSymbolAddress((void**)&buf1, g_buf1);
    float* buf2; cudaGetSymbolAddress((void**)&buf2, g_buf2);
    float4* pb1; cudaGetSymbolAddress((void**)&pb1, g_pb1);
    float4* pb2; cudaGetSymbolAddress((void**)&pb2, g_pb2);
    float4* pb3; cudaGetSymbolAddress((void**)&pb3, g_pb3);

    const int* src = ei;
    const int* dst = ei + E;

    // one-time host-side setup
    static cudaStream_t s2 = nullptr;
    static cudaEvent_t ev_fork = nullptr, ev_join = nullptr;
    static cudaEvent_t evA1, evB1, evGa, evGb, evA2, evB2, evGc, evGd;
    if (!s2) {
        cudaFuncSetAttribute(mma_gemm_kernel<128>,
                             cudaFuncAttributeMaxDynamicSharedMemorySize, A_SMEM_BYTES);
        cudaFuncSetAttribute(mma_gemm_kernel<64>,
                             cudaFuncAttributeMaxDynamicSharedMemorySize, A_SMEM_BYTES);
        cudaStreamCreateWithFlags(&s2, cudaStreamNonBlocking);
        cudaEventCreateWithFlags(&ev_fork, cudaEventDisableTiming);
        cudaEventCreateWithFlags(&ev_join, cudaEventDisableTiming);
        cudaEventCreateWithFlags(&evA1, cudaEventDisableTiming);
        cudaEventCreateWithFlags(&evB1, cudaEventDisableTiming);
        cudaEventCreateWithFlags(&evGa, cudaEventDisableTiming);
        cudaEventCreateWithFlags(&evGb, cudaEventDisableTiming);
        cudaEventCreateWithFlags(&evA2, cudaEventDisableTiming);
        cudaEventCreateWithFlags(&evB2, cudaEventDisableTiming);
        cudaEventCreateWithFlags(&evGc, cudaEventDisableTiming);
        cudaEventCreateWithFlags(&evGd, cudaEventDisableTiming);
    }

    int nb = (N + 1023) / 1024;
    int e4 = (E + 3) / 4;
    int gM = (N + 127) / 128;
    int gW = (N * 32 + 255) / 256;
    int packTotal = 16 * 128 * 4 + 16 * 128 * 4 + 16 * 64 * 4;

    // chunking for agg/gemm pipelining
    int gh1 = gM / 2, gh2 = gM - gh1;
    int Nh = gh1 * 128;                    // chunk-A node count (multiple of 128)
    int gWa = (Nh * 32 + 255) / 256;
    int gWb = ((N - Nh) * 32 + 255) / 256;

    // ---- fork: side stream runs pack + GEMM1; main runs CSR build ----
    cudaEventRecord(ev_fork, 0);
    cudaStreamWaitEvent(s2, ev_fork, 0);

    pack_all_kernel<<<(packTotal + 255) / 256, 256, 0, s2>>>(W1, W2, W3);
    mma_gemm_kernel<128><<<gM, 256, A_SMEM_BYTES, s2>>>(x, pb1, buf0, N, 0);
    cudaEventRecord(ev_join, s2);

    zero_deg_kernel<<<(N + 255) / 256, 256>>>(N);
    deg_kernel<<<(e4 + 255) / 256, 256>>>(dst, E, N);
    scan1_kernel<<<nb, 256>>>(N);
    scan2_kernel<<<1, 32>>>(nb, N);
    scan3_kernel<<<nb, 256>>>(N);
    fill_kernel<<<(e4 + 255) / 256, 256>>>(src, dst, E, N);

    cudaStreamWaitEvent(0, ev_join, 0);

    // ---- layer 1->2 transition, pipelined ----
    // agg1: buf0 -> buf1 ; gemm2: buf1 -> buf2
    agg128_kernel<true><<<gWa, 256>>>(buf0, buf1, b1, 0, Nh);
    cudaEventRecord(evA1, 0);
    cudaStreamWaitEvent(s2, evA1, 0);
    mma_gemm_kernel<128><<<gh1, 256, A_SMEM_BYTES, s2>>>(buf1, pb2, buf2, N, 0);
    cudaEventRecord(evGa, s2);
    agg128_kernel<true><<<gWb, 256>>>(buf0, buf1, b1, Nh, N);
    cudaEventRecord(evB1, 0);
    cudaStreamWaitEvent(s2, evB1, 0);
    mma_gemm_kernel<128><<<gh2, 256, A_SMEM_BYTES, s2>>>(buf1, pb2, buf2, N, Nh);
    cudaEventRecord(evGb, s2);

    // ---- layer 2->3 transition, pipelined ----
    // agg2: buf2 -> buf0 ; gemm3: buf0 -> buf1 (D=64 out)
    cudaStreamWaitEvent(0, evGa, 0);
    cudaStreamWaitEvent(0, evGb, 0);
    agg128_kernel<true><<<gWa, 256>>>(buf2, buf0, b2, 0, Nh);
    cudaEventRecord(evA2, 0);
    cudaStreamWaitEvent(s2, evA2, 0);
    mma_gemm_kernel<64><<<gh1, 256, A_SMEM_BYTES, s2>>>(buf0, pb3, buf1, N, 0);
    cudaEventRecord(evGc, s2);
    agg128_kernel<true><<<gWb, 256>>>(buf2, buf0, b2, Nh, N);
    cudaEventRecord(evB2, 0);
    cudaStreamWaitEvent(s2, evB2, 0);
    mma_gemm_kernel<64><<<gh2, 256, A_SMEM_BYTES, s2>>>(buf0, pb3, buf1, N, Nh);
    cudaEventRecord(evGd, s2);

    // ---- final: agg3 (D=64, no relu) + output head ----
    cudaStreamWaitEvent(0, evGc, 0);
    cudaStreamWaitEvent(0, evGd, 0);
    agg64_out_kernel<<<gW, 256>>>(buf1, hout, b3, Wout, bout, out, N);
}

// round 15
// speedup vs baseline: 1.3111x; 1.1255x over previous
#include <cuda_runtime.h>
#include <cuda_fp16.h>
#include <cstdint>

#define NMAX 40000
#define EMAX 640000

// Scratch (device globals: allocation-free per harness rules)
__device__ int   g_deg[NMAX];
__device__ int   g_rowptr[NMAX + 1];
__device__ int   g_cursor[NMAX];
__device__ int   g_col[EMAX];
__device__ float g_dinv[NMAX];
__device__ int   g_bsum[64];
__device__ float g_buf0[(size_t)NMAX * 128];
__device__ float g_buf1[(size_t)NMAX * 128];
// fp16 shadow of gemm outputs (gather payload): 64 uints/row for D=128, 32 for D=64
__device__ unsigned g_h16[(size_t)NMAX * 64];
// Pre-split tf32 fragment-ordered weights: ((kt*BN)+c)*4+qid -> {hi,lo,hi,lo}
__device__ float4 g_pb1[16 * 128 * 4];
__device__ float4 g_pb2[16 * 128 * 4];
__device__ float4 g_pb3[16 * 64 * 4];

// ---------------------------------------------------------------------------
__device__ __forceinline__ float trunc13(float f) {
    return __uint_as_float(__float_as_uint(f) & 0xffffe000u);
}

// ---------------------------------------------------------------------------
// 1) degree count (edges by dst), 4 edges per thread via int4
// ---------------------------------------------------------------------------
__global__ void deg_kernel(const int* __restrict__ dst, int E, int N) {
    int i = blockIdx.x * blockDim.x + threadIdx.x;
    int e0 = i * 4;
    if (e0 + 4 <= E) {
        int4 d4 = *(const int4*)(dst + e0);
        atomicAdd(&g_deg[max(0, min(d4.x, N - 1))], 1);
        atomicAdd(&g_deg[max(0, min(d4.y, N - 1))], 1);
        atomicAdd(&g_deg[max(0, min(d4.z, N - 1))], 1);
        atomicAdd(&g_deg[max(0, min(d4.w, N - 1))], 1);
    } else {
        for (int e = e0; e < E; e++)
            atomicAdd(&g_deg[max(0, min(dst[e], N - 1))], 1);
    }
}

// ---------------------------------------------------------------------------
// 2) hierarchical exclusive scan -> rowptr/cursor + dinv; scan3 RESETS g_deg
//    (so no zero_deg launch is needed; deterministic across graph replays)
// ---------------------------------------------------------------------------
__global__ void scan1_kernel(int N) {
    __shared__ int sh[256];
    int t = threadIdx.x;
    int base = blockIdx.x * 1024 + t * 4;
    int s = 0;
    #pragma unroll
    for (int i = 0; i < 4; i++) if (base + i < N) s += g_deg[base + i];
    sh[t] = s;
    __syncthreads();
    #pragma unroll
    for (int off = 128; off > 0; off >>= 1) {
        if (t < off) sh[t] += sh[t + off];
        __syncthreads();
    }
    if (t == 0) g_bsum[blockIdx.x] = sh[0];
}

__global__ void scan2_kernel(int nb, int N) {
    if (threadIdx.x == 0) {
        int run = 0;
        for (int i = 0; i < nb; i++) { int v = g_bsum[i]; g_bsum[i] = run; run += v; }
        g_rowptr[N] = run;
    }
}

__global__ void scan3_kernel(int N) {
    __shared__ int sh[256];
    int t = threadIdx.x;
    int base = blockIdx.x * 1024 + t * 4;
    int v[4];
    int s = 0;
    #pragma unroll
    for (int i = 0; i < 4; i++) {
        v[i] = (base + i < N) ? g_deg[base + i] : 0;
        s += v[i];
    }
    sh[t] = s;
    __syncthreads();
    #pragma unroll
    for (int off = 1; off < 256; off <<= 1) {
        int x = (t >= off) ? sh[t - off] : 0;
        __syncthreads();
        sh[t] += x;
        __syncthreads();
    }
    int run = g_bsum[blockIdx.x] + sh[t] - s;
    #pragma unroll
    for (int i = 0; i < 4; i++) {
        int idx = base + i;
        if (idx < N) {
            g_rowptr[idx] = run;
            g_cursor[idx] = run;
            g_dinv[idx]   = rsqrtf((float)v[i] + 1.0f);
            g_deg[idx]    = 0;              // reset for next replay
            run += v[i];
        }
    }
}

// ---------------------------------------------------------------------------
// 3) CSR fill, 4 edges per thread via int4
// ---------------------------------------------------------------------------
__global__ void fill_kernel(const int* __restrict__ src,
                            const int* __restrict__ dst, int E, int N) {
    int i = blockIdx.x * blockDim.x + threadIdx.x;
    int e0 = i * 4;
    if (e0 + 4 <= E) {
        int4 d4 = *(const int4*)(dst + e0);
        int4 s4 = *(const int4*)(src + e0);
        int p0 = atomicAdd(&g_cursor[max(0, min(d4.x, N - 1))], 1);
        int p1 = atomicAdd(&g_cursor[max(0, min(d4.y, N - 1))], 1);
        int p2 = atomicAdd(&g_cursor[max(0, min(d4.z, N - 1))], 1);
        int p3 = atomicAdd(&g_cursor[max(0, min(d4.w, N - 1))], 1);
        g_col[p0] = max(0, min(s4.x, N - 1));
        g_col[p1] = max(0, min(s4.y, N - 1));
        g_col[p2] = max(0, min(s4.z, N - 1));
        g_col[p3] = max(0, min(s4.w, N - 1));
    } else {
        for (int e = e0; e < E; e++) {
            int pos = atomicAdd(&g_cursor[max(0, min(dst[e], N - 1))], 1);
            g_col[pos] = max(0, min(src[e], N - 1));
        }
    }
}

// ---------------------------------------------------------------------------
// 3b) pack ALL weights into fragment-ordered split form, single launch
// ---------------------------------------------------------------------------
__device__ __forceinline__ void pack_one(const float* __restrict__ W,
                                         float4* __restrict__ PB, int BN, int i) {
    int qid = i & 3;
    int c   = (i >> 2) % BN;
    int kt  = (i >> 2) / BN;
    float f0 = W[(kt * 8 + qid) * BN + c];
    float f1 = W[(kt * 8 + qid + 4) * BN + c];
    float4 v;
    v.x = trunc13(f0); v.y = f0 - v.x;
    v.z = trunc13(f1); v.w = f1 - v.z;
    PB[i] = v;
}

__global__ void pack_all_kernel(const float* __restrict__ W1,
                                const float* __restrict__ W2,
                                const float* __restrict__ W3) {
    int i = blockIdx.x * blockDim.x + threadIdx.x;
    if (i < 16 * 128 * 4) { pack_one(W1, g_pb1, 128, i); return; }
    i -= 16 * 128 * 4;
    if (i < 16 * 128 * 4) { pack_one(W2, g_pb2, 128, i); return; }
    i -= 16 * 128 * 4;
    if (i < 16 * 64 * 4)  { pack_one(W3, g_pb3, 64, i); }
}

// ---------------------------------------------------------------------------
// 4) Tensor-core GEMM, 3xTF32, A staged through smem; epilogue writes fp32 C
//    and an fp16x2 shadow H16 (gather payload for the next aggregation)
// ---------------------------------------------------------------------------
__device__ __forceinline__ void mma_tf32(float* c, const unsigned* a, const unsigned* b) {
    asm volatile(
        "mma.sync.aligned.m16n8k8.row.col.f32.tf32.tf32.f32 "
        "{%0,%1,%2,%3}, {%4,%5,%6,%7}, {%8,%9}, {%0,%1,%2,%3};\n"
        : "+f"(c[0]), "+f"(c[1]), "+f"(c[2]), "+f"(c[3])
        : "r"(a[0]), "r"(a[1]), "r"(a[2]), "r"(a[3]), "r"(b[0]), "r"(b[1]));
}

#define A_STRIDE 132   // floats per row (128 + 4 pad -> conflict-free LDS)
#define A_SMEM_BYTES (128 * A_STRIDE * 4)

template <int BN>
__global__ void __launch_bounds__(256, 1)
mma_gemm_kernel(const float* __restrict__ A,
                const float4* __restrict__ PB,
                float* __restrict__ C,
                unsigned* __restrict__ H16, int M) {
    constexpr int NT = BN / 16;
    extern __shared__ float As[];
    int tid = threadIdx.x;
    int wid = tid >> 5, lane = tid & 31;
    int warp_m = wid >> 1, warp_n = wid & 1;
    int grp = lane >> 2, qid = lane & 3;
    int m0 = blockIdx.x * 128;
    int col0 = warp_n * (BN / 2);

    // stage A tile: coalesced float4 loads
    for (int idx = tid; idx < 128 * 32; idx += 256) {
        int r = idx >> 5;
        int c4 = (idx & 31) * 4;
        int gr = min(m0 + r, M - 1);
        *(float4*)(As + r * A_STRIDE + c4) = *(const float4*)(A + (size_t)gr * 128 + c4);
    }
    __syncthreads();

    float acc[2][NT][4];
    #pragma unroll
    for (int mt = 0; mt < 2; mt++)
        #pragma unroll
        for (int nt = 0; nt < NT; nt++)
            #pragma unroll
            for (int j = 0; j < 4; j++) acc[mt][nt][j] = 0.f;

    int ar0 = warp_m * 32 + grp;
    #pragma unroll 2
    for (int kt = 0; kt < 16; kt++) {
        int k0 = kt * 8;
        unsigned ahi[2][4], alo[2][4];
        #pragma unroll
        for (int mt = 0; mt < 2; mt++) {
            int r0 = ar0 + mt * 16;
            int r1 = r0 + 8;
            float f0 = As[r0 * A_STRIDE + k0 + qid];
            float f1 = As[r1 * A_STRIDE + k0 + qid];
            float f2 = As[r0 * A_STRIDE + k0 + qid + 4];
            float f3 = As[r1 * A_STRIDE + k0 + qid + 4];
            float h0 = trunc13(f0), h1 = trunc13(f1), h2 = trunc13(f2), h3 = trunc13(f3);
            ahi[mt][0] = __float_as_uint(h0); alo[mt][0] = __float_as_uint(f0 - h0);
            ahi[mt][1] = __float_as_uint(h1); alo[mt][1] = __float_as_uint(f1 - h1);
            ahi[mt][2] = __float_as_uint(h2); alo[mt][2] = __float_as_uint(f2 - h2);
            ahi[mt][3] = __float_as_uint(h3); alo[mt][3] = __float_as_uint(f3 - h3);
        }
        #pragma unroll
        for (int nt = 0; nt < NT; nt++) {
            int c = col0 + nt * 8 + grp;
            float4 pb = PB[((kt * BN) + c) * 4 + qid];
            unsigned bh[2] = { __float_as_uint(pb.x), __float_as_uint(pb.z) };
            unsigned bl[2] = { __float_as_uint(pb.y), __float_as_uint(pb.w) };
            #pragma unroll
            for (int mt = 0; mt < 2; mt++) {
                mma_tf32(acc[mt][nt], ahi[mt], bh);
                mma_tf32(acc[mt][nt], ahi[mt], bl);
                mma_tf32(acc[mt][nt], alo[mt], bh);
            }
        }
    }
    #pragma unroll
    for (int mt = 0; mt < 2; mt++) {
        int r0 = m0 + warp_m * 32 + mt * 16 + grp;
        int r1 = r0 + 8;
        #pragma unroll
        for (int nt = 0; nt < NT; nt++) {
            int c = col0 + nt * 8 + qid * 2;
            if (r0 < M) {
                C[(size_t)r0 * BN + c]     = acc[mt][nt][0];
                C[(size_t)r0 * BN + c + 1] = acc[mt][nt][1];
                __half2 h = __floats2half2_rn(acc[mt][nt][0], acc[mt][nt][1]);
                H16[(size_t)r0 * (BN / 2) + (c >> 1)] = *(unsigned*)&h;
            }
            if (r1 < M) {
                C[(size_t)r1 * BN + c]     = acc[mt][nt][2];
                C[(size_t)r1 * BN + c + 1] = acc[mt][nt][3];
                __half2 h = __floats2half2_rn(acc[mt][nt][2], acc[mt][nt][3]);
                H16[(size_t)r1 * (BN / 2) + (c >> 1)] = *(unsigned*)&h;
            }
        }
    }
}

// ---------------------------------------------------------------------------
// 5) Aggregation D=128: self from fp32, edges gathered from fp16 shadow
// ---------------------------------------------------------------------------
template <bool RELU>
__global__ void agg128_kernel(const float* __restrict__ hin,
                              const unsigned* __restrict__ h16,
                              float* __restrict__ hout,
                              const float* __restrict__ bias, int N) {
    int warp = (blockIdx.x * blockDim.x + threadIdx.x) >> 5;
    int lane = threadIdx.x & 31;
    if (warp >= N) return;

    float dn = g_dinv[warp];
    float acc[4];
    {
        float ws = dn * dn;
        float4 v = *(const float4*)(hin + (size_t)warp * 128 + lane * 4);
        acc[0] = ws * v.x; acc[1] = ws * v.y; acc[2] = ws * v.z; acc[3] = ws * v.w;
    }
    int e = g_rowptr[warp];
    const int e1 = g_rowptr[warp + 1];
    for (; e + 4 <= e1; e += 4) {
        int s0 = g_col[e], s1 = g_col[e + 1], s2 = g_col[e + 2], s3 = g_col[e + 3];
        float w0 = g_dinv[s0] * dn, w1 = g_dinv[s1] * dn;
        float w2 = g_dinv[s2] * dn, w3 = g_dinv[s3] * dn;
        uint2 u0 = *(const uint2*)(h16 + (size_t)s0 * 64 + lane * 2);
        uint2 u1 = *(const uint2*)(h16 + (size_t)s1 * 64 + lane * 2);
        uint2 u2 = *(const uint2*)(h16 + (size_t)s2 * 64 + lane * 2);
        uint2 u3 = *(const uint2*)(h16 + (size_t)s3 * 64 + lane * 2);
        float2 a0 = __half22float2(*(__half2*)&u0.x), b0 = __half22float2(*(__half2*)&u0.y);
        float2 a1 = __half22float2(*(__half2*)&u1.x), b1v = __half22float2(*(__half2*)&u1.y);
        float2 a2 = __half22float2(*(__half2*)&u2.x), b2v = __half22float2(*(__half2*)&u2.y);
        float2 a3 = __half22float2(*(__half2*)&u3.x), b3v = __half22float2(*(__half2*)&u3.y);
        acc[0] += w0 * a0.x + w1 * a1.x + w2 * a2.x + w3 * a3.x;
        acc[1] += w0 * a0.y + w1 * a1.y + w2 * a2.y + w3 * a3.y;
        acc[2] += w0 * b0.x + w1 * b1v.x + w2 * b2v.x + w3 * b3v.x;
        acc[3] += w0 * b0.y + w1 * b1v.y + w2 * b2v.y + w3 * b3v.y;
    }
    for (; e < e1; e++) {
        int s = g_col[e];
        float w = g_dinv[s] * dn;
        uint2 u = *(const uint2*)(h16 + (size_t)s * 64 + lane * 2);
        float2 a = __half22float2(*(__half2*)&u.x);
        float2 b = __half22float2(*(__half2*)&u.y);
        acc[0] += w * a.x; acc[1] += w * a.y; acc[2] += w * b.x; acc[3] += w * b.y;
    }
    float4 b = *(const float4*)(bias + lane * 4);
    float4 o = make_float4(acc[0] + b.x, acc[1] + b.y, acc[2] + b.z, acc[3] + b.w);
    if (RELU) {
        o.x = fmaxf(o.x, 0.f); o.y = fmaxf(o.y, 0.f);
        o.z = fmaxf(o.z, 0.f); o.w = fmaxf(o.w, 0.f);
    }
    *(float4*)(hout + (size_t)warp * 128 + lane * 4) = o;
}

// ---------------------------------------------------------------------------
// 5b) Aggregation D=64 + fused output head: edges from fp16 shadow (stride 32)
// ---------------------------------------------------------------------------
__global__ void agg64_out_kernel(const float* __restrict__ hin,
                                 const unsigned* __restrict__ h16,
                                 float* __restrict__ hout,
                                 const float* __restrict__ bias,
                                 const float* __restrict__ Wout,
                                 const float* __restrict__ bout,
                                 float* __restrict__ out, int N) {
    int warp = (blockIdx.x * blockDim.x + threadIdx.x) >> 5;
    int lane = threadIdx.x & 31;
    if (warp >= N) return;

    float dn = g_dinv[warp];
    float a0, a1;
    {
        float ws = dn * dn;
        float2 v = *(const float2*)(hin + (size_t)warp * 64 + lane * 2);
        a0 = ws * v.x; a1 = ws * v.y;
    }
    int e = g_rowptr[warp];
    const int e1 = g_rowptr[warp + 1];
    for (; e + 4 <= e1; e += 4) {
        int s0 = g_col[e], s1 = g_col[e + 1], s2 = g_col[e + 2], s3 = g_col[e + 3];
        float w0 = g_dinv[s0] * dn, w1 = g_dinv[s1] * dn;
        float w2 = g_dinv[s2] * dn, w3 = g_dinv[s3] * dn;
        unsigned u0 = h16[(size_t)s0 * 32 + lane];
        unsigned u1 = h16[(size_t)s1 * 32 + lane];
        unsigned u2 = h16[(size_t)s2 * 32 + lane];
        unsigned u3 = h16[(size_t)s3 * 32 + lane];
        float2 v0 = __half22float2(*(__half2*)&u0);
        float2 v1 = __half22float2(*(__half2*)&u1);
        float2 v2 = __half22float2(*(__half2*)&u2);
        float2 v3 = __half22float2(*(__half2*)&u3);
        a0 += w0 * v0.x + w1 * v1.x + w2 * v2.x + w3 * v3.x;
        a1 += w0 * v0.y + w1 * v1.y + w2 * v2.y + w3 * v3.y;
    }
    for (; e < e1; e++) {
        int s = g_col[e];
        float w = g_dinv[s] * dn;
        unsigned u = h16[(size_t)s * 32 + lane];
        float2 v = __half22float2(*(__half2*)&u);
        a0 += w * v.x; a1 += w * v.y;
    }
    float2 b = *(const float2*)(bias + lane * 2);
    float2 o = make_float2(a0 + b.x, a1 + b.y);
    *(float2*)(hout + (size_t)warp * 64 + lane * 2) = o;

    int c0 = lane * 2;
    float p0 = o.x * __ldg(&Wout[c0 * 2])     + o.y * __ldg(&Wout[(c0 + 1) * 2]);
    float p1 = o.x * __ldg(&Wout[c0 * 2 + 1]) + o.y * __ldg(&Wout[(c0 + 1) * 2 + 1]);
    #pragma unroll
    for (int off = 16; off > 0; off >>= 1) {
        p0 += __shfl_xor_sync(0xffffffffu, p0, off);
        p1 += __shfl_xor_sync(0xffffffffu, p1, off);
    }
    if (lane == 0) {
        out[(size_t)warp * 2 + 0] = p0 + __ldg(&bout[0]);
        out[(size_t)warp * 2 + 1] = p1 + __ldg(&bout[1]);
    }
}

// ---------------------------------------------------------------------------
extern "C" void kernel_launch(void* const* d_in, const int* in_sizes, int n_in,
                              void* d_out, int out_size) {
    (void)n_in; (void)out_size;
    const float* x    = (const float*)d_in[0];
    const int*   ei   = (const int*)d_in[1];   // int32 (JAX default x64 off)
    const float* W1   = (const float*)d_in[2];
    const float* b1   = (const float*)d_in[3];
    const float* W2   = (const float*)d_in[4];
    const float* b2   = (const float*)d_in[5];
    const float* W3   = (const float*)d_in[6];
    const float* b3   = (const float*)d_in[7];
    const float* Wout = (const float*)d_in[8];
    const float* bout = (const float*)d_in[9];

    int N = in_sizes[0] / 128;
    int E = in_sizes[1] / 2;

    float* out  = (float*)d_out;
    float* hout = out + (size_t)N * 2;   // tuple layout: out[N,2] then h[N,64]

    float* buf0; cudaGetSymbolAddress((void**)&buf0, g_buf0);
    float* buf1; cudaGetSymbolAddress((void**)&buf1, g_buf1);
    unsigned* h16; cudaGetSymbolAddress((void**)&h16, g_h16);
    float4* pb1; cudaGetSymbolAddress((void**)&pb1, g_pb1);
    float4* pb2; cudaGetSymbolAddress((void**)&pb2, g_pb2);
    float4* pb3; cudaGetSymbolAddress((void**)&pb3, g_pb3);

    const int* src = ei;
    const int* dst = ei + E;

    // one-time host-side setup (attrs, side stream, fork/join events)
    static cudaStream_t s2 = nullptr;
    static cudaEvent_t ev_fork = nullptr, ev_join = nullptr;
    if (!s2) {
        cudaFuncSetAttribute(mma_gemm_kernel<128>,
                             cudaFuncAttributeMaxDynamicSharedMemorySize, A_SMEM_BYTES);
        cudaFuncSetAttribute(mma_gemm_kernel<64>,
                             cudaFuncAttributeMaxDynamicSharedMemorySize, A_SMEM_BYTES);
        cudaStreamCreateWithFlags(&s2, cudaStreamNonBlocking);
        cudaEventCreateWithFlags(&ev_fork, cudaEventDisableTiming);
        cudaEventCreateWithFlags(&ev_join, cudaEventDisableTiming);
    }

    int nb = (N + 1023) / 1024;
    int e4 = (E + 3) / 4;
    int gM = (N + 127) / 128;
    int gW = (N * 32 + 255) / 256;
    int packTotal = 16 * 128 * 4 + 16 * 128 * 4 + 16 * 64 * 4;

    // ---- fork: side stream runs pack + GEMM1; main runs CSR build ----
    cudaEventRecord(ev_fork, 0);
    cudaStreamWaitEvent(s2, ev_fork, 0);

    // branch B (s2): pack_all -> gemm1
    pack_all_kernel<<<(packTotal + 255) / 256, 256, 0, s2>>>(W1, W2, W3);
    mma_gemm_kernel<128><<<gM, 256, A_SMEM_BYTES, s2>>>(x, pb1, buf0, h16, N);
    cudaEventRecord(ev_join, s2);

    // branch A (capture stream): CSR build (deg array pre-zeroed by prior
    // replay's scan3; module load zeroes it initially)
    deg_kernel<<<(e4 + 255) / 256, 256>>>(dst, E, N);
    scan1_kernel<<<nb, 256>>>(N);
    scan2_kernel<<<1, 32>>>(nb, N);
    scan3_kernel<<<nb, 256>>>(N);
    fill_kernel<<<(e4 + 255) / 256, 256>>>(src, dst, E, N);

    // ---- join ----
    cudaStreamWaitEvent(0, ev_join, 0);

    // Layer 1 agg + layer 2
    agg128_kernel<true><<<gW, 256>>>(buf0, h16, buf1, b1, N);
    mma_gemm_kernel<128><<<gM, 256, A_SMEM_BYTES>>>(buf1, pb2, buf0, h16, N);
    agg128_kernel<true><<<gW, 256>>>(buf0, h16, buf1, b2, N);
    // Layer 3 (D=64) + fused output head
    mma_gemm_kernel<64><<<gM, 256, A_SMEM_BYTES>>>(buf1, pb3, buf0, h16, N);
    agg64_out_kernel<<<gW, 256>>>(buf0, h16, hout, b3, Wout, bout, out, N);
}

// round 16
// speedup vs baseline: 1.3518x; 1.0311x over previous
#include <cuda_runtime.h>
#include <cstdint>

#define NMAX 40000
#define EMAX 640000

// Scratch (device globals: allocation-free per harness rules)
__device__ int   g_deg[NMAX];
__device__ int   g_rowptr[NMAX + 1];
__device__ int   g_cursor[NMAX];
__device__ int   g_col[EMAX];
__device__ float g_dinv[NMAX];
__device__ int   g_bsum[64];
__device__ float g_buf0[(size_t)NMAX * 128];
__device__ float g_buf1[(size_t)NMAX * 128];
// Pre-split tf32 fragment-ordered weights: ((kt*BN)+c)*4+qid -> {hi,lo,hi,lo}
__device__ float4 g_pb1[16 * 128 * 4];
__device__ float4 g_pb2[16 * 128 * 4];
__device__ float4 g_pb3[16 * 64 * 4];

// ---------------------------------------------------------------------------
__device__ __forceinline__ float trunc13(float f) {
    return __uint_as_float(__float_as_uint(f) & 0xffffe000u);
}

// ---------------------------------------------------------------------------
// 1) degree count (edges by dst), 4 edges per thread via int4
//    (g_deg is zero at module load and re-zeroed by scan3 each replay)
// ---------------------------------------------------------------------------
__global__ void deg_kernel(const int* __restrict__ dst, int E, int N) {
    int i = blockIdx.x * blockDim.x + threadIdx.x;
    int e0 = i * 4;
    if (e0 + 4 <= E) {
        int4 d4 = *(const int4*)(dst + e0);
        atomicAdd(&g_deg[max(0, min(d4.x, N - 1))], 1);
        atomicAdd(&g_deg[max(0, min(d4.y, N - 1))], 1);
        atomicAdd(&g_deg[max(0, min(d4.z, N - 1))], 1);
        atomicAdd(&g_deg[max(0, min(d4.w, N - 1))], 1);
    } else {
        for (int e = e0; e < E; e++)
            atomicAdd(&g_deg[max(0, min(dst[e], N - 1))], 1);
    }
}

// ---------------------------------------------------------------------------
// 1b) dinv from deg (needed early: GEMM epilogues scale rows by dinv)
// ---------------------------------------------------------------------------
__global__ void dinv_kernel(int N) {
    int i = blockIdx.x * blockDim.x + threadIdx.x;
    if (i < N) g_dinv[i] = rsqrtf((float)g_deg[i] + 1.0f);   // +1 = self-loop
}

// ---------------------------------------------------------------------------
// 2) hierarchical exclusive scan -> rowptr/cursor; scan3 RESETS g_deg
// ---------------------------------------------------------------------------
__global__ void scan1_kernel(int N) {
    __shared__ int sh[256];
    int t = threadIdx.x;
    int base = blockIdx.x * 1024 + t * 4;
    int s = 0;
    #pragma unroll
    for (int i = 0; i < 4; i++) if (base + i < N) s += g_deg[base + i];
    sh[t] = s;
    __syncthreads();
    #pragma unroll
    for (int off = 128; off > 0; off >>= 1) {
        if (t < off) sh[t] += sh[t + off];
        __syncthreads();
    }
    if (t == 0) g_bsum[blockIdx.x] = sh[0];
}

__global__ void scan2_kernel(int nb, int N) {
    if (threadIdx.x == 0) {
        int run = 0;
        for (int i = 0; i < nb; i++) { int v = g_bsum[i]; g_bsum[i] = run; run += v; }
        g_rowptr[N] = run;
    }
}

__global__ void scan3_kernel(int N) {
    __shared__ int sh[256];
    int t = threadIdx.x;
    int base = blockIdx.x * 1024 + t * 4;
    int v[4];
    int s = 0;
    #pragma unroll
    for (int i = 0; i < 4; i++) {
        v[i] = (base + i < N) ? g_deg[base + i] : 0;
        s += v[i];
    }
    sh[t] = s;
    __syncthreads();
    #pragma unroll
    for (int off = 1; off < 256; off <<= 1) {
        int x = (t >= off) ? sh[t - off] : 0;
        __syncthreads();
        sh[t] += x;
        __syncthreads();
    }
    int run = g_bsum[blockIdx.x] + sh[t] - s;
    #pragma unroll
    for (int i = 0; i < 4; i++) {
        int idx = base + i;
        if (idx < N) {
            g_rowptr[idx] = run;
            g_cursor[idx] = run;
            g_deg[idx]    = 0;              // reset for next replay
            run += v[i];
        }
    }
}

// ---------------------------------------------------------------------------
// 3) CSR fill, 4 edges per thread via int4
// ---------------------------------------------------------------------------
__global__ void fill_kernel(const int* __restrict__ src,
                            const int* __restrict__ dst, int E, int N) {
    int i = blockIdx.x * blockDim.x + threadIdx.x;
    int e0 = i * 4;
    if (e0 + 4 <= E) {
        int4 d4 = *(const int4*)(dst + e0);
        int4 s4 = *(const int4*)(src + e0);
        int p0 = atomicAdd(&g_cursor[max(0, min(d4.x, N - 1))], 1);
        int p1 = atomicAdd(&g_cursor[max(0, min(d4.y, N - 1))], 1);
        int p2 = atomicAdd(&g_cursor[max(0, min(d4.z, N - 1))], 1);
        int p3 = atomicAdd(&g_cursor[max(0, min(d4.w, N - 1))], 1);
        g_col[p0] = max(0, min(s4.x, N - 1));
        g_col[p1] = max(0, min(s4.y, N - 1));
        g_col[p2] = max(0, min(s4.z, N - 1));
        g_col[p3] = max(0, min(s4.w, N - 1));
    } else {
        for (int e = e0; e < E; e++) {
            int pos = atomicAdd(&g_cursor[max(0, min(dst[e], N - 1))], 1);
            g_col[pos] = max(0, min(src[e], N - 1));
        }
    }
}

// ---------------------------------------------------------------------------
// 3b) pack ALL weights into fragment-ordered split form, single launch
// ---------------------------------------------------------------------------
__device__ __forceinline__ void pack_one(const float* __restrict__ W,
                                         float4* __restrict__ PB, int BN, int i) {
    int qid = i & 3;
    int c   = (i >> 2) % BN;
    int kt  = (i >> 2) / BN;
    float f0 = W[(kt * 8 + qid) * BN + c];
    float f1 = W[(kt * 8 + qid + 4) * BN + c];
    float4 v;
    v.x = trunc13(f0); v.y = f0 - v.x;
    v.z = trunc13(f1); v.w = f1 - v.z;
    PB[i] = v;
}

__global__ void pack_all_kernel(const float* __restrict__ W1,
                                const float* __restrict__ W2,
                                const float* __restrict__ W3) {
    int i = blockIdx.x * blockDim.x + threadIdx.x;
    if (i < 16 * 128 * 4) { pack_one(W1, g_pb1, 128, i); return; }
    i -= 16 * 128 * 4;
    if (i < 16 * 128 * 4) { pack_one(W2, g_pb2, 128, i); return; }
    i -= 16 * 128 * 4;
    if (i < 16 * 64 * 4)  { pack_one(W3, g_pb3, 64, i); }
}

// ---------------------------------------------------------------------------
// 4) Tensor-core GEMM, 3xTF32, A staged through smem.
//    Epilogue writes dinv[row] * result (pre-scaled features for the agg).
// ---------------------------------------------------------------------------
__device__ __forceinline__ void mma_tf32(float* c, const unsigned* a, const unsigned* b) {
    asm volatile(
        "mma.sync.aligned.m16n8k8.row.col.f32.tf32.tf32.f32 "
        "{%0,%1,%2,%3}, {%4,%5,%6,%7}, {%8,%9}, {%0,%1,%2,%3};\n"
        : "+f"(c[0]), "+f"(c[1]), "+f"(c[2]), "+f"(c[3])
        : "r"(a[0]), "r"(a[1]), "r"(a[2]), "r"(a[3]), "r"(b[0]), "r"(b[1]));
}

#define A_STRIDE 132   // floats per row (128 + 4 pad -> conflict-free LDS)
#define A_SMEM_BYTES (128 * A_STRIDE * 4)

template <int BN>
__global__ void __launch_bounds__(256, 1)
mma_gemm_kernel(const float* __restrict__ A,
                const float4* __restrict__ PB,
                float* __restrict__ C, int M) {
    constexpr int NT = BN / 16;
    extern __shared__ float As[];
    int tid = threadIdx.x;
    int wid = tid >> 5, lane = tid & 31;
    int warp_m = wid >> 1, warp_n = wid & 1;
    int grp = lane >> 2, qid = lane & 3;
    int m0 = blockIdx.x * 128;
    int col0 = warp_n * (BN / 2);

    // stage A tile: coalesced float4 loads
    for (int idx = tid; idx < 128 * 32; idx += 256) {
        int r = idx >> 5;
        int c4 = (idx & 31) * 4;
        int gr = min(m0 + r, M - 1);
        *(float4*)(As + r * A_STRIDE + c4) = *(const float4*)(A + (size_t)gr * 128 + c4);
    }
    __syncthreads();

    float acc[2][NT][4];
    #pragma unroll
    for (int mt = 0; mt < 2; mt++)
        #pragma unroll
        for (int nt = 0; nt < NT; nt++)
            #pragma unroll
            for (int j = 0; j < 4; j++) acc[mt][nt][j] = 0.f;

    int ar0 = warp_m * 32 + grp;
    #pragma unroll 2
    for (int kt = 0; kt < 16; kt++) {
        int k0 = kt * 8;
        unsigned ahi[2][4], alo[2][4];
        #pragma unroll
        for (int mt = 0; mt < 2; mt++) {
            int r0 = ar0 + mt * 16;
            int r1 = r0 + 8;
            float f0 = As[r0 * A_STRIDE + k0 + qid];
            float f1 = As[r1 * A_STRIDE + k0 + qid];
            float f2 = As[r0 * A_STRIDE + k0 + qid + 4];
            float f3 = As[r1 * A_STRIDE + k0 + qid + 4];
            float h0 = trunc13(f0), h1 = trunc13(f1), h2 = trunc13(f2), h3 = trunc13(f3);
            ahi[mt][0] = __float_as_uint(h0); alo[mt][0] = __float_as_uint(f0 - h0);
            ahi[mt][1] = __float_as_uint(h1); alo[mt][1] = __float_as_uint(f1 - h1);
            ahi[mt][2] = __float_as_uint(h2); alo[mt][2] = __float_as_uint(f2 - h2);
            ahi[mt][3] = __float_as_uint(h3); alo[mt][3] = __float_as_uint(f3 - h3);
        }
        #pragma unroll
        for (int nt = 0; nt < NT; nt++) {
            int c = col0 + nt * 8 + grp;
            float4 pb = PB[((kt * BN) + c) * 4 + qid];
            unsigned bh[2] = { __float_as_uint(pb.x), __float_as_uint(pb.z) };
            unsigned bl[2] = { __float_as_uint(pb.y), __float_as_uint(pb.w) };
            #pragma unroll
            for (int mt = 0; mt < 2; mt++) {
                mma_tf32(acc[mt][nt], ahi[mt], bh);
                mma_tf32(acc[mt][nt], ahi[mt], bl);
                mma_tf32(acc[mt][nt], alo[mt], bh);
            }
        }
    }
    #pragma unroll
    for (int mt = 0; mt < 2; mt++) {
        int r0 = m0 + warp_m * 32 + mt * 16 + grp;
        int r1 = r0 + 8;
        float d0 = (r0 < M) ? g_dinv[r0] : 0.f;
        float d1 = (r1 < M) ? g_dinv[r1] : 0.f;
        #pragma unroll
        for (int nt = 0; nt < NT; nt++) {
            int c = col0 + nt * 8 + qid * 2;
            if (r0 < M) {
                C[(size_t)r0 * BN + c]     = d0 * acc[mt][nt][0];
                C[(size_t)r0 * BN + c + 1] = d0 * acc[mt][nt][1];
            }
            if (r1 < M) {
                C[(size_t)r1 * BN + c]     = d1 * acc[mt][nt][2];
                C[(size_t)r1 * BN + c + 1] = d1 * acc[mt][nt][3];
            }
        }
    }
}

// ---------------------------------------------------------------------------
// 5) Aggregation D=128 on PRE-SCALED features: acc = self + sum(edges),
//    out = dn*acc + bias (optional ReLU). No per-edge dinv load or multiply.
// ---------------------------------------------------------------------------
template <bool RELU>
__global__ void agg128_kernel(const float* __restrict__ hin,
                              float* __restrict__ hout,
                              const float* __restrict__ bias, int N) {
    int warp = (blockIdx.x * blockDim.x + threadIdx.x) >> 5;
    int lane = threadIdx.x & 31;
    if (warp >= N) return;

    float acc[4];
    {
        float4 v = *(const float4*)(hin + (size_t)warp * 128 + lane * 4);
        acc[0] = v.x; acc[1] = v.y; acc[2] = v.z; acc[3] = v.w;
    }
    int e = g_rowptr[warp];
    const int e1 = g_rowptr[warp + 1];
    for (; e + 4 <= e1; e += 4) {
        int s0 = g_col[e], s1 = g_col[e + 1], s2 = g_col[e + 2], s3 = g_col[e + 3];
        float4 v0 = *(const float4*)(hin + (size_t)s0 * 128 + lane * 4);
        float4 v1 = *(const float4*)(hin + (size_t)s1 * 128 + lane * 4);
        float4 v2 = *(const float4*)(hin + (size_t)s2 * 128 + lane * 4);
        float4 v3 = *(const float4*)(hin + (size_t)s3 * 128 + lane * 4);
        acc[0] += v0.x + v1.x + v2.x + v3.x;
        acc[1] += v0.y + v1.y + v2.y + v3.y;
        acc[2] += v0.z + v1.z + v2.z + v3.z;
        acc[3] += v0.w + v1.w + v2.w + v3.w;
    }
    for (; e < e1; e++) {
        int s = g_col[e];
        float4 v = *(const float4*)(hin + (size_t)s * 128 + lane * 4);
        acc[0] += v.x; acc[1] += v.y; acc[2] += v.z; acc[3] += v.w;
    }
    float dn = g_dinv[warp];
    float4 b = *(const float4*)(bias + lane * 4);
    float4 o = make_float4(dn * acc[0] + b.x, dn * acc[1] + b.y,
                           dn * acc[2] + b.z, dn * acc[3] + b.w);
    if (RELU) {
        o.x = fmaxf(o.x, 0.f); o.y = fmaxf(o.y, 0.f);
        o.z = fmaxf(o.z, 0.f); o.w = fmaxf(o.w, 0.f);
    }
    *(float4*)(hout + (size_t)warp * 128 + lane * 4) = o;
}

// ---------------------------------------------------------------------------
// 5b) Aggregation D=64 (pre-scaled input) + fused output head
// ---------------------------------------------------------------------------
__global__ void agg64_out_kernel(const float* __restrict__ hin,
                                 float* __restrict__ hout,
                                 const float* __restrict__ bias,
                                 const float* __restrict__ Wout,
                                 const float* __restrict__ bout,
                                 float* __restrict__ out, int N) {
    int warp = (blockIdx.x * blockDim.x + threadIdx.x) >> 5;
    int lane = threadIdx.x & 31;
    if (warp >= N) return;

    float a0, a1;
    {
        float2 v = *(const float2*)(hin + (size_t)warp * 64 + lane * 2);
        a0 = v.x; a1 = v.y;
    }
    int e = g_rowptr[warp];
    const int e1 = g_rowptr[warp + 1];
    for (; e + 4 <= e1; e += 4) {
        int s0 = g_col[e], s1 = g_col[e + 1], s2 = g_col[e + 2], s3 = g_col[e + 3];
        float2 v0 = *(const float2*)(hin + (size_t)s0 * 64 + lane * 2);
        float2 v1 = *(const float2*)(hin + (size_t)s1 * 64 + lane * 2);
        float2 v2 = *(const float2*)(hin + (size_t)s2 * 64 + lane * 2);
        float2 v3 = *(const float2*)(hin + (size_t)s3 * 64 + lane * 2);
        a0 += v0.x + v1.x + v2.x + v3.x;
        a1 += v0.y + v1.y + v2.y + v3.y;
    }
    for (; e < e1; e++) {
        int s = g_col[e];
        float2 v = *(const float2*)(hin + (size_t)s * 64 + lane * 2);
        a0 += v.x; a1 += v.y;
    }
    float dn = g_dinv[warp];
    float2 b = *(const float2*)(bias + lane * 2);
    float2 o = make_float2(dn * a0 + b.x, dn * a1 + b.y);
    *(float2*)(hout + (size_t)warp * 64 + lane * 2) = o;

    int c0 = lane * 2;
    float p0 = o.x * __ldg(&Wout[c0 * 2])     + o.y * __ldg(&Wout[(c0 + 1) * 2]);
    float p1 = o.x * __ldg(&Wout[c0 * 2 + 1]) + o.y * __ldg(&Wout[(c0 + 1) * 2 + 1]);
    #pragma unroll
    for (int off = 16; off > 0; off >>= 1) {
        p0 += __shfl_xor_sync(0xffffffffu, p0, off);
        p1 += __shfl_xor_sync(0xffffffffu, p1, off);
    }
    if (lane == 0) {
        out[(size_t)warp * 2 + 0] = p0 + __ldg(&bout[0]);
        out[(size_t)warp * 2 + 1] = p1 + __ldg(&bout[1]);
    }
}

// ---------------------------------------------------------------------------
extern "C" void kernel_launch(void* const* d_in, const int* in_sizes, int n_in,
                              void* d_out, int out_size) {
    (void)n_in; (void)out_size;
    const float* x    = (const float*)d_in[0];
    const int*   ei   = (const int*)d_in[1];   // int32 (JAX default x64 off)
    const float* W1   = (const float*)d_in[2];
    const float* b1   = (const float*)d_in[3];
    const float* W2   = (const float*)d_in[4];
    const float* b2   = (const float*)d_in[5];
    const float* W3   = (const float*)d_in[6];
    const float* b3   = (const float*)d_in[7];
    const float* Wout = (const float*)d_in[8];
    const float* bout = (const float*)d_in[9];

    int N = in_sizes[0] / 128;
    int E = in_sizes[1] / 2;

    float* out  = (float*)d_out;
    float* hout = out + (size_t)N * 2;   // tuple layout: out[N,2] then h[N,64]

    float* buf0; cudaGetSymbolAddress((void**)&buf0, g_buf0);
    float* buf1; cudaGetSymbolAddress((void**)&buf1, g_buf1);
    float4* pb1; cudaGetSymbolAddress((void**)&pb1, g_pb1);
    float4* pb2; cudaGetSymbolAddress((void**)&pb2, g_pb2);
    float4* pb3; cudaGetSymbolAddress((void**)&pb3, g_pb3);

    const int* src = ei;
    const int* dst = ei + E;

    // one-time host-side setup (attrs, side stream, events)
    static cudaStream_t s2 = nullptr;
    static cudaEvent_t ev_fork = nullptr, ev_join = nullptr, ev_dinv = nullptr;
    if (!s2) {
        cudaFuncSetAttribute(mma_gemm_kernel<128>,
                             cudaFuncAttributeMaxDynamicSharedMemorySize, A_SMEM_BYTES);
        cudaFuncSetAttribute(mma_gemm_kernel<64>,
                             cudaFuncAttributeMaxDynamicSharedMemorySize, A_SMEM_BYTES);
        cudaStreamCreateWithFlags(&s2, cudaStreamNonBlocking);
        cudaEventCreateWithFlags(&ev_fork, cudaEventDisableTiming);
        cudaEventCreateWithFlags(&ev_join, cudaEventDisableTiming);
        cudaEventCreateWithFlags(&ev_dinv, cudaEventDisableTiming);
    }

    int nb = (N + 1023) / 1024;
    int e4 = (E + 3) / 4;
    int gM = (N + 127) / 128;
    int gW = (N * 32 + 255) / 256;
    int packTotal = 16 * 128 * 4 + 16 * 128 * 4 + 16 * 64 * 4;

    // ---- fork ----
    cudaEventRecord(ev_fork, 0);
    cudaStreamWaitEvent(s2, ev_fork, 0);

    // branch B (s2): pack_all; then (after dinv ready) gemm1 with scaled epilogue
    pack_all_kernel<<<(packTotal + 255) / 256, 256, 0, s2>>>(W1, W2, W3);

    // branch A (capture stream): deg -> dinv -> scans -> fill
    deg_kernel<<<(e4 + 255) / 256, 256>>>(dst, E, N);
    dinv_kernel<<<(N + 255) / 256, 256>>>(N);
    cudaEventRecord(ev_dinv, 0);
    cudaStreamWaitEvent(s2, ev_dinv, 0);
    mma_gemm_kernel<128><<<gM, 256, A_SMEM_BYTES, s2>>>(x, pb1, buf0, N);
    cudaEventRecord(ev_join, s2);

    scan1_kernel<<<nb, 256>>>(N);
    scan2_kernel<<<1, 32>>>(nb, N);
    scan3_kernel<<<nb, 256>>>(N);
    fill_kernel<<<(e4 + 255) / 256, 256>>>(src, dst, E, N);

    // ---- join ----
    cudaStreamWaitEvent(0, ev_join, 0);

    // Layer 1 agg + layer 2
    agg128_kernel<true><<<gW, 256>>>(buf0, buf1, b1, N);
    mma_gemm_kernel<128><<<gM, 256, A_SMEM_BYTES>>>(buf1, pb2, buf0, N);
    agg128_kernel<true><<<gW, 256>>>(buf0, buf1, b2, N);
    // Layer 3 (D=64) + fused output head
    mma_gemm_kernel<64><<<gM, 256, A_SMEM_BYTES>>>(buf1, pb3, buf0, N);
    agg64_out_kernel<<<gW, 256>>>(buf0, hout, b3, Wout, bout, out, N);
}

// round 17
// speedup vs baseline: 1.4339x; 1.0607x over previous
#include <cuda_runtime.h>
#include <cstdint>

#define NMAX 40000
#define EMAX 640000

// Scratch (device globals: allocation-free per harness rules)
__device__ int   g_deg[NMAX];
__device__ int   g_rowptr[NMAX + 1];
__device__ int   g_cursor[NMAX];
__device__ int   g_col[EMAX];
__device__ float g_dinv[NMAX];
__device__ int   g_bsum[64];
__device__ float g_buf0[(size_t)NMAX * 128];
__device__ float g_buf1[(size_t)NMAX * 128];
// Pre-split tf32 fragment-ordered weights: ((kt*BN)+c)*4+qid -> {hi,lo,hi,lo}
__device__ float4 g_pb1[16 * 128 * 4];
__device__ float4 g_pb2[16 * 128 * 4];
__device__ float4 g_pb3[16 * 64 * 4];

// ---------------------------------------------------------------------------
__device__ __forceinline__ float trunc13(float f) {
    return __uint_as_float(__float_as_uint(f) & 0xffffe000u);
}

// ---------------------------------------------------------------------------
// 1) degree count (edges by dst), 4 edges per thread via int4
//    (g_deg is zero at module load and re-zeroed by scan3 each replay)
// ---------------------------------------------------------------------------
__global__ void deg_kernel(const int* __restrict__ dst, int E, int N) {
    int i = blockIdx.x * blockDim.x + threadIdx.x;
    int e0 = i * 4;
    if (e0 + 4 <= E) {
        int4 d4 = *(const int4*)(dst + e0);
        atomicAdd(&g_deg[max(0, min(d4.x, N - 1))], 1);
        atomicAdd(&g_deg[max(0, min(d4.y, N - 1))], 1);
        atomicAdd(&g_deg[max(0, min(d4.z, N - 1))], 1);
        atomicAdd(&g_deg[max(0, min(d4.w, N - 1))], 1);
    } else {
        for (int e = e0; e < E; e++)
            atomicAdd(&g_deg[max(0, min(dst[e], N - 1))], 1);
    }
}

// ---------------------------------------------------------------------------
// 1b) dinv from deg (needed early: GEMM epilogues scale rows by dinv)
// ---------------------------------------------------------------------------
__global__ void dinv_kernel(int N) {
    int i = blockIdx.x * blockDim.x + threadIdx.x;
    if (i < N) g_dinv[i] = rsqrtf((float)g_deg[i] + 1.0f);   // +1 = self-loop
}

// ---------------------------------------------------------------------------
// 2) hierarchical exclusive scan -> rowptr/cursor; scan3 RESETS g_deg
// ---------------------------------------------------------------------------
__global__ void scan1_kernel(int N) {
    __shared__ int sh[256];
    int t = threadIdx.x;
    int base = blockIdx.x * 1024 + t * 4;
    int s = 0;
    #pragma unroll
    for (int i = 0; i < 4; i++) if (base + i < N) s += g_deg[base + i];
    sh[t] = s;
    __syncthreads();
    #pragma unroll
    for (int off = 128; off > 0; off >>= 1) {
        if (t < off) sh[t] += sh[t + off];
        __syncthreads();
    }
    if (t == 0) g_bsum[blockIdx.x] = sh[0];
}

__global__ void scan2_kernel(int nb, int N) {
    if (threadIdx.x == 0) {
        int run = 0;
        for (int i = 0; i < nb; i++) { int v = g_bsum[i]; g_bsum[i] = run; run += v; }
        g_rowptr[N] = run;
    }
}

__global__ void scan3_kernel(int N) {
    __shared__ int sh[256];
    int t = threadIdx.x;
    int base = blockIdx.x * 1024 + t * 4;
    int v[4];
    int s = 0;
    #pragma unroll
    for (int i = 0; i < 4; i++) {
        v[i] = (base + i < N) ? g_deg[base + i] : 0;
        s += v[i];
    }
    sh[t] = s;
    __syncthreads();
    #pragma unroll
    for (int off = 1; off < 256; off <<= 1) {
        int x = (t >= off) ? sh[t - off] : 0;
        __syncthreads();
        sh[t] += x;
        __syncthreads();
    }
    int run = g_bsum[blockIdx.x] + sh[t] - s;
    #pragma unroll
    for (int i = 0; i < 4; i++) {
        int idx = base + i;
        if (idx < N) {
            g_rowptr[idx] = run;
            g_cursor[idx] = run;
            g_deg[idx]    = 0;              // reset for next replay
            run += v[i];
        }
    }
}

// ---------------------------------------------------------------------------
// 3) CSR fill, 4 edges per thread via int4
// ---------------------------------------------------------------------------
__global__ void fill_kernel(const int* __restrict__ src,
                            const int* __restrict__ dst, int E, int N) {
    int i = blockIdx.x * blockDim.x + threadIdx.x;
    int e0 = i * 4;
    if (e0 + 4 <= E) {
        int4 d4 = *(const int4*)(dst + e0);
        int4 s4 = *(const int4*)(src + e0);
        int p0 = atomicAdd(&g_cursor[max(0, min(d4.x, N - 1))], 1);
        int p1 = atomicAdd(&g_cursor[max(0, min(d4.y, N - 1))], 1);
        int p2 = atomicAdd(&g_cursor[max(0, min(d4.z, N - 1))], 1);
        int p3 = atomicAdd(&g_cursor[max(0, min(d4.w, N - 1))], 1);
        g_col[p0] = max(0, min(s4.x, N - 1));
        g_col[p1] = max(0, min(s4.y, N - 1));
        g_col[p2] = max(0, min(s4.z, N - 1));
        g_col[p3] = max(0, min(s4.w, N - 1));
    } else {
        for (int e = e0; e < E; e++) {
            int pos = atomicAdd(&g_cursor[max(0, min(dst[e], N - 1))], 1);
            g_col[pos] = max(0, min(src[e], N - 1));
        }
    }
}

// ---------------------------------------------------------------------------
// 3b) pack ALL weights into fragment-ordered split form, single launch
// ---------------------------------------------------------------------------
__device__ __forceinline__ void pack_one(const float* __restrict__ W,
                                         float4* __restrict__ PB, int BN, int i) {
    int qid = i & 3;
    int c   = (i >> 2) % BN;
    int kt  = (i >> 2) / BN;
    float f0 = W[(kt * 8 + qid) * BN + c];
    float f1 = W[(kt * 8 + qid + 4) * BN + c];
    float4 v;
    v.x = trunc13(f0); v.y = f0 - v.x;
    v.z = trunc13(f1); v.w = f1 - v.z;
    PB[i] = v;
}

__global__ void pack_all_kernel(const float* __restrict__ W1,
                                const float* __restrict__ W2,
                                const float* __restrict__ W3) {
    int i = blockIdx.x * blockDim.x + threadIdx.x;
    if (i < 16 * 128 * 4) { pack_one(W1, g_pb1, 128, i); return; }
    i -= 16 * 128 * 4;
    if (i < 16 * 128 * 4) { pack_one(W2, g_pb2, 128, i); return; }
    i -= 16 * 128 * 4;
    if (i < 16 * 64 * 4)  { pack_one(W3, g_pb3, 64, i); }
}

// ---------------------------------------------------------------------------
// 4) Tensor-core GEMM, 3xTF32, BM=64 block tile (3 blocks/SM target).
//    8 warps: warp_m = wid>>1 (4 x 16 rows), warp_n = wid&1 (2 x BN/2 cols).
//    Epilogue writes dinv[row] * result (pre-scaled features for the agg).
// ---------------------------------------------------------------------------
__device__ __forceinline__ void mma_tf32(float* c, const unsigned* a, const unsigned* b) {
    asm volatile(
        "mma.sync.aligned.m16n8k8.row.col.f32.tf32.tf32.f32 "
        "{%0,%1,%2,%3}, {%4,%5,%6,%7}, {%8,%9}, {%0,%1,%2,%3};\n"
        : "+f"(c[0]), "+f"(c[1]), "+f"(c[2]), "+f"(c[3])
        : "r"(a[0]), "r"(a[1]), "r"(a[2]), "r"(a[3]), "r"(b[0]), "r"(b[1]));
}

#define A_STRIDE 132   // floats per row (128 + 4 pad -> conflict-free LDS)
#define A_SMEM_BYTES (64 * A_STRIDE * 4)

template <int BN>
__global__ void __launch_bounds__(256, 3)
mma_gemm_kernel(const float* __restrict__ A,
                const float4* __restrict__ PB,
                float* __restrict__ C, int M) {
    constexpr int NT = BN / 16;
    extern __shared__ float As[];   // [64][A_STRIDE]
    int tid = threadIdx.x;
    int wid = tid >> 5, lane = tid & 31;
    int warp_m = wid >> 1, warp_n = wid & 1;
    int grp = lane >> 2, qid = lane & 3;
    int m0 = blockIdx.x * 64;
    int col0 = warp_n * (BN / 2);

    // stage A tile (64 rows): coalesced float4 loads
    for (int idx = tid; idx < 64 * 32; idx += 256) {
        int r = idx >> 5;
        int c4 = (idx & 31) * 4;
        int gr = min(m0 + r, M - 1);
        *(float4*)(As + r * A_STRIDE + c4) = *(const float4*)(A + (size_t)gr * 128 + c4);
    }
    __syncthreads();

    float acc[NT][4];
    #pragma unroll
    for (int nt = 0; nt < NT; nt++)
        #pragma unroll
        for (int j = 0; j < 4; j++) acc[nt][j] = 0.f;

    int ar0 = warp_m * 16 + grp;       // local row (m16 tile)
    #pragma unroll 2
    for (int kt = 0; kt < 16; kt++) {
        int k0 = kt * 8;
        unsigned ahi[4], alo[4];
        {
            int r0 = ar0;
            int r1 = r0 + 8;
            float f0 = As[r0 * A_STRIDE + k0 + qid];
            float f1 = As[r1 * A_STRIDE + k0 + qid];
            float f2 = As[r0 * A_STRIDE + k0 + qid + 4];
            float f3 = As[r1 * A_STRIDE + k0 + qid + 4];
            float h0 = trunc13(f0), h1 = trunc13(f1), h2 = trunc13(f2), h3 = trunc13(f3);
            ahi[0] = __float_as_uint(h0); alo[0] = __float_as_uint(f0 - h0);
            ahi[1] = __float_as_uint(h1); alo[1] = __float_as_uint(f1 - h1);
            ahi[2] = __float_as_uint(h2); alo[2] = __float_as_uint(f2 - h2);
            ahi[3] = __float_as_uint(h3); alo[3] = __float_as_uint(f3 - h3);
        }
        #pragma unroll
        for (int nt = 0; nt < NT; nt++) {
            int c = col0 + nt * 8 + grp;
            float4 pb = PB[((kt * BN) + c) * 4 + qid];
            unsigned bh[2] = { __float_as_uint(pb.x), __float_as_uint(pb.z) };
            unsigned bl[2] = { __float_as_uint(pb.y), __float_as_uint(pb.w) };
            mma_tf32(acc[nt], ahi, bh);
            mma_tf32(acc[nt], ahi, bl);
            mma_tf32(acc[nt], alo, bh);
        }
    }
    {
        int r0 = m0 + warp_m * 16 + grp;
        int r1 = r0 + 8;
        float d0 = (r0 < M) ? g_dinv[r0] : 0.f;
        float d1 = (r1 < M) ? g_dinv[r1] : 0.f;
        #pragma unroll
        for (int nt = 0; nt < NT; nt++) {
            int c = col0 + nt * 8 + qid * 2;
            if (r0 < M) {
                C[(size_t)r0 * BN + c]     = d0 * acc[nt][0];
                C[(size_t)r0 * BN + c + 1] = d0 * acc[nt][1];
            }
            if (r1 < M) {
                C[(size_t)r1 * BN + c]     = d1 * acc[nt][2];
                C[(size_t)r1 * BN + c + 1] = d1 * acc[nt][3];
            }
        }
    }
}

// ---------------------------------------------------------------------------
// 5) Aggregation D=128 on PRE-SCALED features: acc = self + sum(edges),
//    out = dn*acc + bias (optional ReLU). No per-edge dinv load or multiply.
// ---------------------------------------------------------------------------
template <bool RELU>
__global__ void agg128_kernel(const float* __restrict__ hin,
                              float* __restrict__ hout,
                              const float* __restrict__ bias, int N) {
    int warp = (blockIdx.x * blockDim.x + threadIdx.x) >> 5;
    int lane = threadIdx.x & 31;
    if (warp >= N) return;

    float acc[4];
    {
        float4 v = *(const float4*)(hin + (size_t)warp * 128 + lane * 4);
        acc[0] = v.x; acc[1] = v.y; acc[2] = v.z; acc[3] = v.w;
    }
    int e = g_rowptr[warp];
    const int e1 = g_rowptr[warp + 1];
    for (; e + 4 <= e1; e += 4) {
        int s0 = g_col[e], s1 = g_col[e + 1], s2 = g_col[e + 2], s3 = g_col[e + 3];
        float4 v0 = *(const float4*)(hin + (size_t)s0 * 128 + lane * 4);
        float4 v1 = *(const float4*)(hin + (size_t)s1 * 128 + lane * 4);
        float4 v2 = *(const float4*)(hin + (size_t)s2 * 128 + lane * 4);
        float4 v3 = *(const float4*)(hin + (size_t)s3 * 128 + lane * 4);
        acc[0] += v0.x + v1.x + v2.x + v3.x;
        acc[1] += v0.y + v1.y + v2.y + v3.y;
        acc[2] += v0.z + v1.z + v2.z + v3.z;
        acc[3] += v0.w + v1.w + v2.w + v3.w;
    }
    for (; e < e1; e++) {
        int s = g_col[e];
        float4 v = *(const float4*)(hin + (size_t)s * 128 + lane * 4);
        acc[0] += v.x; acc[1] += v.y; acc[2] += v.z; acc[3] += v.w;
    }
    float dn = g_dinv[warp];
    float4 b = *(const float4*)(bias + lane * 4);
    float4 o = make_float4(dn * acc[0] + b.x, dn * acc[1] + b.y,
                           dn * acc[2] + b.z, dn * acc[3] + b.w);
    if (RELU) {
        o.x = fmaxf(o.x, 0.f); o.y = fmaxf(o.y, 0.f);
        o.z = fmaxf(o.z, 0.f); o.w = fmaxf(o.w, 0.f);
    }
    *(float4*)(hout + (size_t)warp * 128 + lane * 4) = o;
}

// ---------------------------------------------------------------------------
// 5b) Aggregation D=64 (pre-scaled input) + fused output head
// ---------------------------------------------------------------------------
__global__ void agg64_out_kernel(const float* __restrict__ hin,
                                 float* __restrict__ hout,
                                 const float* __restrict__ bias,
                                 const float* __restrict__ Wout,
                                 const float* __restrict__ bout,
                                 float* __restrict__ out, int N) {
    int warp = (blockIdx.x * blockDim.x + threadIdx.x) >> 5;
    int lane = threadIdx.x & 31;
    if (warp >= N) return;

    float a0, a1;
    {
        float2 v = *(const float2*)(hin + (size_t)warp * 64 + lane * 2);
        a0 = v.x; a1 = v.y;
    }
    int e = g_rowptr[warp];
    const int e1 = g_rowptr[warp + 1];
    for (; e + 4 <= e1; e += 4) {
        int s0 = g_col[e], s1 = g_col[e + 1], s2 = g_col[e + 2], s3 = g_col[e + 3];
        float2 v0 = *(const float2*)(hin + (size_t)s0 * 64 + lane * 2);
        float2 v1 = *(const float2*)(hin + (size_t)s1 * 64 + lane * 2);
        float2 v2 = *(const float2*)(hin + (size_t)s2 * 64 + lane * 2);
        float2 v3 = *(const float2*)(hin + (size_t)s3 * 64 + lane * 2);
        a0 += v0.x + v1.x + v2.x + v3.x;
        a1 += v0.y + v1.y + v2.y + v3.y;
    }
    for (; e < e1; e++) {
        int s = g_col[e];
        float2 v = *(const float2*)(hin + (size_t)s * 64 + lane * 2);
        a0 += v.x; a1 += v.y;
    }
    float dn = g_dinv[warp];
    float2 b = *(const float2*)(bias + lane * 2);
    float2 o = make_float2(dn * a0 + b.x, dn * a1 + b.y);
    *(float2*)(hout + (size_t)warp * 64 + lane * 2) = o;

    int c0 = lane * 2;
    float p0 = o.x * __ldg(&Wout[c0 * 2])     + o.y * __ldg(&Wout[(c0 + 1) * 2]);
    float p1 = o.x * __ldg(&Wout[c0 * 2 + 1]) + o.y * __ldg(&Wout[(c0 + 1) * 2 + 1]);
    #pragma unroll
    for (int off = 16; off > 0; off >>= 1) {
        p0 += __shfl_xor_sync(0xffffffffu, p0, off);
        p1 += __shfl_xor_sync(0xffffffffu, p1, off);
    }
    if (lane == 0) {
        out[(size_t)warp * 2 + 0] = p0 + __ldg(&bout[0]);
        out[(size_t)warp * 2 + 1] = p1 + __ldg(&bout[1]);
    }
}

// ---------------------------------------------------------------------------
extern "C" void kernel_launch(void* const* d_in, const int* in_sizes, int n_in,
                              void* d_out, int out_size) {
    (void)n_in; (void)out_size;
    const float* x    = (const float*)d_in[0];
    const int*   ei   = (const int*)d_in[1];   // int32 (JAX default x64 off)
    const float* W1   = (const float*)d_in[2];
    const float* b1   = (const float*)d_in[3];
    const float* W2   = (const float*)d_in[4];
    const float* b2   = (const float*)d_in[5];
    const float* W3   = (const float*)d_in[6];
    const float* b3   = (const float*)d_in[7];
    const float* Wout = (const float*)d_in[8];
    const float* bout = (const float*)d_in[9];

    int N = in_sizes[0] / 128;
    int E = in_sizes[1] / 2;

    float* out  = (float*)d_out;
    float* hout = out + (size_t)N * 2;   // tuple layout: out[N,2] then h[N,64]

    float* buf0; cudaGetSymbolAddress((void**)&buf0, g_buf0);
    float* buf1; cudaGetSymbolAddress((void**)&buf1, g_buf1);
    float4* pb1; cudaGetSymbolAddress((void**)&pb1, g_pb1);
    float4* pb2; cudaGetSymbolAddress((void**)&pb2, g_pb2);
    float4* pb3; cudaGetSymbolAddress((void**)&pb3, g_pb3);

    const int* src = ei;
    const int* dst = ei + E;

    // one-time host-side setup (attrs, side stream, events)
    static cudaStream_t s2 = nullptr;
    static cudaEvent_t ev_fork = nullptr, ev_join = nullptr, ev_dinv = nullptr;
    if (!s2) {
        cudaFuncSetAttribute(mma_gemm_kernel<128>,
                             cudaFuncAttributeMaxDynamicSharedMemorySize, A_SMEM_BYTES);
        cudaFuncSetAttribute(mma_gemm_kernel<64>,
                             cudaFuncAttributeMaxDynamicSharedMemorySize, A_SMEM_BYTES);
        cudaStreamCreateWithFlags(&s2, cudaStreamNonBlocking);
        cudaEventCreateWithFlags(&ev_fork, cudaEventDisableTiming);
        cudaEventCreateWithFlags(&ev_join, cudaEventDisableTiming);
        cudaEventCreateWithFlags(&ev_dinv, cudaEventDisableTiming);
    }

    int nb = (N + 1023) / 1024;
    int e4 = (E + 3) / 4;
    int gM = (N + 63) / 64;                 // BM=64 tiles
    int gW = (N * 32 + 255) / 256;
    int packTotal = 16 * 128 * 4 + 16 * 128 * 4 + 16 * 64 * 4;

    // ---- fork ----
    cudaEventRecord(ev_fork, 0);
    cudaStreamWaitEvent(s2, ev_fork, 0);

    // branch B (s2): pack_all; then (after dinv ready) gemm1 with scaled epilogue
    pack_all_kernel<<<(packTotal + 255) / 256, 256, 0, s2>>>(W1, W2, W3);

    // branch A (capture stream): deg -> dinv -> scans -> fill
    deg_kernel<<<(e4 + 255) / 256, 256>>>(dst, E, N);
    dinv_kernel<<<(N + 255) / 256, 256>>>(N);
    cudaEventRecord(ev_dinv, 0);
    cudaStreamWaitEvent(s2, ev_dinv, 0);
    mma_gemm_kernel<128><<<gM, 256, A_SMEM_BYTES, s2>>>(x, pb1, buf0, N);
    cudaEventRecord(ev_join, s2);

    scan1_kernel<<<nb, 256>>>(N);
    scan2_kernel<<<1, 32>>>(nb, N);
    scan3_kernel<<<nb, 256>>>(N);
    fill_kernel<<<(e4 + 255) / 256, 256>>>(src, dst, E, N);

    // ---- join ----
    cudaStreamWaitEvent(0, ev_join, 0);

    // Layer 1 agg + layer 2
    agg128_kernel<true><<<gW, 256>>>(buf0, buf1, b1, N);
    mma_gemm_kernel<128><<<gM, 256, A_SMEM_BYTES>>>(buf1, pb2, buf0, N);
    agg128_kernel<true><<<gW, 256>>>(buf0, buf1, b2, N);
    // Layer 3 (D=64) + fused output head
    mma_gemm_kernel<64><<<gM, 256, A_SMEM_BYTES>>>(buf1, pb3, buf0, N);
    agg64_out_kernel<<<gW, 256>>>(buf0, hout, b3, Wout, bout, out, N);
}